// round 5
// baseline (speedup 1.0000x reference)
#include <cuda_runtime.h>
#include <cuda_bf16.h>
#include <cuda_fp16.h>
#include <cstdint>

// VQ-VAE nearest-codebook quantization.
//   idx[n] = argmin_k (||cb_k||^2 - 2 z_n . cb_k);  zq = cb[idx];  z_st = zq + (z - zq)
// Coarse: bf16 mma.sync GEMM -> fp16 d2 + per-256-code block minima.
// Rescue: all k with coarse d2 < coarse_min + MARGIN get exact fp32 rescore.

#define NTOK 4096
#define DDIM 1024
#define CAP_CAND (1 << 18)
#define MARGIN 3.0f
#define KBLK 16           // 4096 / 256 code-blocks

__device__ unsigned long long g_best[NTOK];     // coarse packed (ord(d2)<<32)|k
__device__ unsigned long long g_final[NTOK];    // exact packed
__device__ float g_cbnorm[NTOK];
__device__ float g_nrm_part[16][NTOK];
__device__ float g_blockmin[NTOK * KBLK];       // coarse min per (token, 256-code block)
__device__ float g_Zt[(size_t)NTOK * DDIM];     // fp32 token-major (rescore)
__device__ float g_CBt[(size_t)NTOK * DDIM];
__device__ __align__(16) __nv_bfloat16 g_Zh[(size_t)NTOK * DDIM];
__device__ __align__(16) __nv_bfloat16 g_CBh[(size_t)NTOK * DDIM];
__device__ __half g_d2h[(size_t)NTOK * NTOK];   // coarse d2 [token][code], fp16
__device__ unsigned g_cand[CAP_CAND];
__device__ unsigned g_ncand;

// ---- helpers ----
__device__ __forceinline__ uint32_t smem_u32(const void* p) {
    uint32_t a;
    asm("{ .reg .u64 t; cvta.to.shared.u64 t, %1; cvt.u32.u64 %0, t; }" : "=r"(a) : "l"(p));
    return a;
}
__device__ __forceinline__ unsigned order_f32(float f) {
    unsigned u = __float_as_uint(f);
    return (u & 0x80000000u) ? ~u : (u | 0x80000000u);
}
__device__ __forceinline__ float unorder_f32(unsigned u) {
    return (u & 0x80000000u) ? __uint_as_float(u ^ 0x80000000u) : __uint_as_float(~u);
}
__device__ __forceinline__ void cp_async16(uint32_t dst, const void* src) {
    asm volatile("cp.async.cg.shared.global [%0], [%1], 16;" :: "r"(dst), "l"(src));
}
__device__ __forceinline__ void cp_commit() { asm volatile("cp.async.commit_group;"); }
__device__ __forceinline__ void cp_wait0()  { asm volatile("cp.async.wait_group 0;"); }
__device__ __forceinline__ void ldsm4(uint32_t (&r)[4], uint32_t addr) {
    asm volatile("ldmatrix.sync.aligned.m8n8.x4.shared.b16 {%0,%1,%2,%3}, [%4];"
                 : "=r"(r[0]), "=r"(r[1]), "=r"(r[2]), "=r"(r[3]) : "r"(addr));
}
__device__ __forceinline__ void mma16816(float (&c)[4], const uint32_t (&a)[4],
                                         uint32_t b0, uint32_t b1) {
    asm volatile(
        "mma.sync.aligned.m16n8k16.row.col.f32.bf16.bf16.f32 "
        "{%0,%1,%2,%3}, {%4,%5,%6,%7}, {%8,%9}, {%0,%1,%2,%3};"
        : "+f"(c[0]), "+f"(c[1]), "+f"(c[2]), "+f"(c[3])
        : "r"(a[0]), "r"(a[1]), "r"(a[2]), "r"(a[3]), "r"(b0), "r"(b1));
}
// Swizzled smem tile: rows x 4 k-granules of 16B; 2 rows per 128B line,
// xor over ((row>>1)&7) -> conflict-free for cp.async stores and ldmatrix.
__device__ __forceinline__ uint32_t sw_addr(uint32_t base, int row, int kg) {
    return base + ((row >> 1) << 7) + ((((kg + ((row & 1) << 2)) ^ ((row >> 1) & 7))) << 4);
}

// ---------------------------------------------------------------------------
__global__ void vq_init() {
    int i = blockIdx.x * 256 + threadIdx.x;
    if (i < NTOK) { g_final[i] = ~0ull; g_best[i] = ~0ull; }
    if (i == 0) g_ncand = 0;
}

// ---------------------------------------------------------------------------
// prep: token-major fp32 + bf16 row-major + partial cb norms (fixed order)
// grid (32 nb, 16 dc, 2 which), 256 threads. Block = 128 cols x 64 dims.
// ---------------------------------------------------------------------------
__global__ void vq_prep(const float* __restrict__ Z, const float* __restrict__ CB) {
    __shared__ float tile[64 * 129];
    const int nb = blockIdx.x, dc = blockIdx.y, which = blockIdx.z;
    const float* src = which ? CB : Z;
    float* dstT = which ? g_CBt : g_Zt;
    __nv_bfloat16* dstH = which ? g_CBh : g_Zh;
    const int tid = threadIdx.x;

    for (int idx = tid; idx < 64 * 128; idx += 256) {
        int d = idx >> 7, n = idx & 127;
        tile[d * 129 + n] = src[(size_t)(dc * 64 + d) * NTOK + nb * 128 + n];
    }
    __syncthreads();
    for (int idx = tid; idx < 64 * 128; idx += 256) {
        int n = idx >> 6, d = idx & 63;
        dstT[(size_t)(nb * 128 + n) * DDIM + dc * 64 + d] = tile[d * 129 + n];
    }
    for (int idx = tid; idx < 64 * 64; idx += 256) {
        int n = idx >> 5, dd = (idx & 31) << 1;
        __nv_bfloat162 h2 = __floats2bfloat162_rn(tile[dd * 129 + n], tile[(dd + 1) * 129 + n]);
        *reinterpret_cast<__nv_bfloat162*>(
            &dstH[(size_t)(nb * 128 + n) * DDIM + dc * 64 + dd]) = h2;
    }
    if (which && tid < 128) {
        float s = 0.f;
        #pragma unroll 8
        for (int d = 0; d < 64; d++) { float v = tile[d * 129 + tid]; s += v * v; }
        g_nrm_part[dc][nb * 128 + tid] = s;
    }
}

__global__ void vq_norm_combine() {
    int k = blockIdx.x * 256 + threadIdx.x;
    float s = 0.f;
    #pragma unroll
    for (int i = 0; i < 16; i++) s += g_nrm_part[i][k];
    g_cbnorm[k] = s;
}

// ---------------------------------------------------------------------------
// coarse GEMM: 128 tokens x 256 codes x K=1024 (32-dim chunks), double-buffered
// cp.async (2 x 24KB = 48KB static smem). 256 threads = 8 warps (2 M x 4 N),
// warp tile 64x64. Epilogue: fp16 d2 + per-token block min.
// ---------------------------------------------------------------------------
#define STG_B 24576     // A 8KB + B 16KB per stage

__global__ __launch_bounds__(256, 1) void vq_gemm() {
    __shared__ __align__(1024) char sm[2 * STG_B];
    const uint32_t smb = smem_u32(sm);
    const int tid = threadIdx.x, wid = tid >> 5, lane = tid & 31;
    const int warp_m = wid & 1, warp_n = wid >> 1;
    const int t0 = blockIdx.x * 128, k0 = blockIdx.y * 256;
    const char* zp = (const char*)g_Zh + (size_t)t0 * DDIM * 2;
    const char* cp = (const char*)g_CBh + (size_t)k0 * DDIM * 2;

    float acc[4][8][4];
    #pragma unroll
    for (int i = 0; i < 4; i++)
        #pragma unroll
        for (int j = 0; j < 8; j++)
            #pragma unroll
            for (int q = 0; q < 4; q++) acc[i][j][q] = 0.f;

    // stage loader: A 512 + B 1024 granules of 16B -> 6 cp.async / thread
    auto load_stage = [&](int stg, int kc) {
        const uint32_t sbase = smb + stg * STG_B;
        #pragma unroll
        for (int u = 0; u < 6; u++) {
            int i = tid + u * 256;
            bool isB = i >= 512;
            int j = isB ? i - 512 : i;
            int r = j >> 2, c = j & 3;
            uint32_t dst = sw_addr(sbase + (isB ? 8192 : 0), r, c);
            const char* src = (isB ? cp : zp) + (size_t)r * 2048 + kc * 64 + c * 16;
            cp_async16(dst, src);
        }
        cp_commit();
    };

    load_stage(0, 0);

    for (int kc = 0; kc < 32; kc++) {
        cp_wait0();                 // stage kc resident
        __syncthreads();            // all compute on the other buffer finished
        if (kc + 1 < 32) load_stage((kc + 1) & 1, kc + 1);

        const uint32_t sA = smb + (kc & 1) * STG_B;
        const uint32_t sB = sA + 8192;
        #pragma unroll
        for (int s = 0; s < 2; s++) {
            uint32_t a[4][4], b[4][4];
            #pragma unroll
            for (int mt = 0; mt < 4; mt++) {
                int row = warp_m * 64 + mt * 16 + ((lane >> 3) & 1) * 8 + (lane & 7);
                int kg = s * 2 + (lane >> 4);
                ldsm4(a[mt], sw_addr(sA, row, kg));
            }
            #pragma unroll
            for (int np = 0; np < 4; np++) {
                int row = warp_n * 64 + np * 16 + ((lane >> 4) << 3) + (lane & 7);
                int kg = s * 2 + ((lane >> 3) & 1);
                ldsm4(b[np], sw_addr(sB, row, kg));
            }
            #pragma unroll
            for (int mt = 0; mt < 4; mt++) {
                #pragma unroll
                for (int np = 0; np < 4; np++) {
                    mma16816(acc[mt][np * 2 + 0], a[mt], b[np][0], b[np][1]);
                    mma16816(acc[mt][np * 2 + 1], a[mt], b[np][2], b[np][3]);
                }
            }
        }
    }
    __syncthreads();

    // ---- epilogue ----
    const int kbase = k0 + warp_n * 64 + (lane & 3) * 2;
    float2 cbn[8];
    #pragma unroll
    for (int nt = 0; nt < 8; nt++)
        cbn[nt] = *reinterpret_cast<const float2*>(&g_cbnorm[kbase + nt * 8]);

    unsigned long long* smin = reinterpret_cast<unsigned long long*>(sm);  // 128*4 u64

    #pragma unroll
    for (int mt = 0; mt < 4; mt++) {
        #pragma unroll
        for (int half = 0; half < 2; half++) {
            const int tl = warp_m * 64 + mt * 16 + half * 8 + (lane >> 2);
            __half* drow = g_d2h + (size_t)(t0 + tl) * NTOK;
            unsigned long long best = ~0ull;
            #pragma unroll
            for (int nt = 0; nt < 8; nt++) {
                float dx = fmaf(-2.f, acc[mt][nt][half * 2 + 0], cbn[nt].x);
                float dy = fmaf(-2.f, acc[mt][nt][half * 2 + 1], cbn[nt].y);
                *reinterpret_cast<__half2*>(&drow[kbase + nt * 8]) = __floats2half2_rn(dx, dy);
                unsigned long long p0 =
                    ((unsigned long long)order_f32(dx) << 32) | (unsigned)(kbase + nt * 8);
                unsigned long long p1 =
                    ((unsigned long long)order_f32(dy) << 32) | (unsigned)(kbase + nt * 8 + 1);
                if (p0 < best) best = p0;
                if (p1 < best) best = p1;
            }
            // reduce over the 4 lanes sharing this t (lane&3)
            {
                unsigned long long v = __shfl_xor_sync(0xFFFFFFFFu, best, 1);
                if (v < best) best = v;
                v = __shfl_xor_sync(0xFFFFFFFFu, best, 2);
                if (v < best) best = v;
            }
            if ((lane & 3) == 0) smin[tl * 4 + warp_n] = best;
        }
    }
    __syncthreads();
    if (tid < 128) {
        unsigned long long b = smin[tid * 4];
        #pragma unroll
        for (int i = 1; i < 4; i++)
            if (smin[tid * 4 + i] < b) b = smin[tid * 4 + i];
        atomicMin(&g_best[t0 + tid], b);
        g_blockmin[(t0 + tid) * KBLK + blockIdx.y] = unorder_f32((unsigned)(b >> 32));
    }
}

// ---------------------------------------------------------------------------
// collect: warp per token; only scan 256-code segments whose blockmin < thr.
// ---------------------------------------------------------------------------
__global__ void vq_collect() {
    const int w = threadIdx.x >> 5, lane = threadIdx.x & 31;
    const int t = blockIdx.x * 8 + w;
    const float thr = unorder_f32((unsigned)(g_best[t] >> 32)) + MARGIN;
    const float* bm = g_blockmin + (size_t)t * KBLK;
    for (int b = 0; b < KBLK; b++) {
        if (bm[b] >= thr) continue;
        const __half2* p = (const __half2*)(g_d2h + (size_t)t * NTOK + b * 256);
        #pragma unroll
        for (int u = 0; u < 4; u++) {
            __half2 v = p[lane * 4 + u];
            float x = __low2float(v), y = __high2float(v);
            int kb = b * 256 + (lane * 4 + u) * 2;
            if (x < thr) {
                unsigned pos = atomicAdd(&g_ncand, 1u);
                if (pos < CAP_CAND) g_cand[pos] = ((unsigned)t << 12) | (unsigned)kb;
            }
            if (y < thr) {
                unsigned pos = atomicAdd(&g_ncand, 1u);
                if (pos < CAP_CAND) g_cand[pos] = ((unsigned)t << 12) | (unsigned)(kb + 1);
            }
        }
    }
}

// ---------------------------------------------------------------------------
// rescore: exact fp32 dot per candidate (one warp each) -> g_final
// ---------------------------------------------------------------------------
__global__ void vq_rescore() {
    const int wg = blockIdx.x * 4 + (threadIdx.x >> 5);
    const int lane = threadIdx.x & 31;
    unsigned cnt = g_ncand; if (cnt > CAP_CAND) cnt = CAP_CAND;
    for (unsigned c = wg; c < cnt; c += gridDim.x * 4) {
        unsigned e = g_cand[c];
        int n = e >> 12, k = e & 4095;
        const float4* za = (const float4*)(g_Zt  + (size_t)n * DDIM);
        const float4* cb = (const float4*)(g_CBt + (size_t)k * DDIM);
        float s = 0.f;
        #pragma unroll
        for (int j = 0; j < 8; j++) {
            float4 a = za[j * 32 + lane], b = cb[j * 32 + lane];
            s = fmaf(a.x, b.x, s); s = fmaf(a.y, b.y, s);
            s = fmaf(a.z, b.z, s); s = fmaf(a.w, b.w, s);
        }
        #pragma unroll
        for (int o = 16; o; o >>= 1) s += __shfl_xor_sync(0xFFFFFFFFu, s, o);
        if (lane == 0) {
            float d2 = fmaf(-2.f, s, g_cbnorm[k]);
            unsigned long long pk = ((unsigned long long)order_f32(d2) << 32) | (unsigned)k;
            atomicMin(&g_final[n], pk);
        }
    }
}

// ---------------------------------------------------------------------------
// gather: contiguous reads of token-major g_CBt + smem transpose.
// grid (32 nb, 16 dc), 256 threads; block = 128 tokens x 64 dims.
// ---------------------------------------------------------------------------
__global__ void vq_gather(const float* __restrict__ Z, float* __restrict__ out, int writeQ) {
    __shared__ float qs[128][65];
    __shared__ int ks[128];
    const int nb = blockIdx.x, dc = blockIdx.y, tid = threadIdx.x;
    if (tid < 128) ks[tid] = (int)(g_final[nb * 128 + tid] & 0xFFFFFFFFu);
    __syncthreads();
    for (int idx = tid; idx < 128 * 64; idx += 256) {
        int n = idx >> 6, d = idx & 63;
        qs[n][d] = g_CBt[(size_t)ks[n] * DDIM + dc * 64 + d];
    }
    __syncthreads();
    float* out_q = out + (size_t)DDIM * NTOK;
    for (int idx = tid; idx < 64 * 128; idx += 256) {
        int d = idx >> 7, n = idx & 127;
        int gd = dc * 64 + d, gn = nb * 128 + n;
        float q = qs[n][d];
        float z = Z[(size_t)gd * NTOK + gn];
        out[(size_t)gd * NTOK + gn] = q + (z - q);
        if (writeQ) out_q[(size_t)gd * NTOK + gn] = q;
    }
}

// ---------------------------------------------------------------------------
extern "C" void kernel_launch(void* const* d_in, const int* in_sizes, int n_in,
                              void* d_out, int out_size) {
    const float* Z  = (const float*)d_in[0];
    const float* CB = (const float*)d_in[1];
    float* out = (float*)d_out;
    const int writeQ = (out_size >= 2 * DDIM * NTOK) ? 1 : 0;

    vq_init<<<16, 256>>>();
    vq_prep<<<dim3(32, 16, 2), 256>>>(Z, CB);
    vq_norm_combine<<<16, 256>>>();
    vq_gemm<<<dim3(32, 16), 256>>>();
    vq_collect<<<512, 256>>>();
    vq_rescore<<<512, 128>>>();
    vq_gather<<<dim3(32, 16), 256>>>(Z, out, writeQ);
}

// round 6
// speedup vs baseline: 1.0001x; 1.0001x over previous
#include <cuda_runtime.h>
#include <cuda_bf16.h>
#include <cuda_fp16.h>
#include <cstdint>

// VQ-VAE nearest-codebook quantization.
//   idx[n] = argmin_k (||cb_k||^2 - 2 z_n . cb_k);  zq = cb[idx];  z_st = zq + (z - zq)
// Coarse: bf16 mma.sync GEMM -> fp16 d2 + per-256-code block minima.
// Rescue: all k with coarse d2 < coarse_min + MARGIN get exact fp32 rescore.

#define NTOK 4096
#define DDIM 1024
#define CAP_CAND (1 << 18)
#define MARGIN 3.0f
#define KBLK 16           // 4096 / 256 code-blocks

__device__ unsigned long long g_best[NTOK];     // coarse packed (ord(d2)<<32)|k
__device__ unsigned long long g_final[NTOK];    // exact packed
__device__ float g_cbnorm[NTOK];
__device__ float g_nrm_part[16][NTOK];
__device__ float g_blockmin[NTOK * KBLK];       // coarse min per (token, 256-code block)
__device__ float g_Zt[(size_t)NTOK * DDIM];     // fp32 token-major (rescore)
__device__ float g_CBt[(size_t)NTOK * DDIM];
__device__ __align__(16) __nv_bfloat16 g_Zh[(size_t)NTOK * DDIM];
__device__ __align__(16) __nv_bfloat16 g_CBh[(size_t)NTOK * DDIM];
__device__ __half g_d2h[(size_t)NTOK * NTOK];   // coarse d2 [token][code], fp16
__device__ unsigned g_cand[CAP_CAND];
__device__ unsigned g_ncand;

// ---- helpers ----
__device__ __forceinline__ uint32_t smem_u32(const void* p) {
    uint32_t a;
    asm("{ .reg .u64 t; cvta.to.shared.u64 t, %1; cvt.u32.u64 %0, t; }" : "=r"(a) : "l"(p));
    return a;
}
__device__ __forceinline__ unsigned order_f32(float f) {
    unsigned u = __float_as_uint(f);
    return (u & 0x80000000u) ? ~u : (u | 0x80000000u);
}
__device__ __forceinline__ float unorder_f32(unsigned u) {
    return (u & 0x80000000u) ? __uint_as_float(u ^ 0x80000000u) : __uint_as_float(~u);
}
__device__ __forceinline__ void cp_async16(uint32_t dst, const void* src) {
    asm volatile("cp.async.cg.shared.global [%0], [%1], 16;" :: "r"(dst), "l"(src));
}
__device__ __forceinline__ void cp_commit() { asm volatile("cp.async.commit_group;"); }
__device__ __forceinline__ void cp_wait0()  { asm volatile("cp.async.wait_group 0;"); }
__device__ __forceinline__ void ldsm4(uint32_t (&r)[4], uint32_t addr) {
    asm volatile("ldmatrix.sync.aligned.m8n8.x4.shared.b16 {%0,%1,%2,%3}, [%4];"
                 : "=r"(r[0]), "=r"(r[1]), "=r"(r[2]), "=r"(r[3]) : "r"(addr));
}
__device__ __forceinline__ void mma16816(float (&c)[4], const uint32_t (&a)[4],
                                         uint32_t b0, uint32_t b1) {
    asm volatile(
        "mma.sync.aligned.m16n8k16.row.col.f32.bf16.bf16.f32 "
        "{%0,%1,%2,%3}, {%4,%5,%6,%7}, {%8,%9}, {%0,%1,%2,%3};"
        : "+f"(c[0]), "+f"(c[1]), "+f"(c[2]), "+f"(c[3])
        : "r"(a[0]), "r"(a[1]), "r"(a[2]), "r"(a[3]), "r"(b0), "r"(b1));
}
// Swizzled smem tile: rows x 4 k-granules of 16B; 2 rows per 128B line,
// xor over ((row>>1)&7) -> conflict-free for cp.async stores and ldmatrix.
__device__ __forceinline__ uint32_t sw_addr(uint32_t base, int row, int kg) {
    return base + ((row >> 1) << 7) + ((((kg + ((row & 1) << 2)) ^ ((row >> 1) & 7))) << 4);
}

// ---------------------------------------------------------------------------
__global__ void vq_init() {
    int i = blockIdx.x * 256 + threadIdx.x;
    if (i < NTOK) { g_final[i] = ~0ull; g_best[i] = ~0ull; }
    if (i == 0) g_ncand = 0;
}

// ---------------------------------------------------------------------------
// prep: token-major fp32 + bf16 row-major + partial cb norms (fixed order)
// grid (32 nb, 16 dc, 2 which), 256 threads. Block = 128 cols x 64 dims.
// ---------------------------------------------------------------------------
__global__ void vq_prep(const float* __restrict__ Z, const float* __restrict__ CB) {
    __shared__ float tile[64 * 129];
    const int nb = blockIdx.x, dc = blockIdx.y, which = blockIdx.z;
    const float* src = which ? CB : Z;
    float* dstT = which ? g_CBt : g_Zt;
    __nv_bfloat16* dstH = which ? g_CBh : g_Zh;
    const int tid = threadIdx.x;

    for (int idx = tid; idx < 64 * 128; idx += 256) {
        int d = idx >> 7, n = idx & 127;
        tile[d * 129 + n] = src[(size_t)(dc * 64 + d) * NTOK + nb * 128 + n];
    }
    __syncthreads();
    for (int idx = tid; idx < 64 * 128; idx += 256) {
        int n = idx >> 6, d = idx & 63;
        dstT[(size_t)(nb * 128 + n) * DDIM + dc * 64 + d] = tile[d * 129 + n];
    }
    for (int idx = tid; idx < 64 * 64; idx += 256) {
        int n = idx >> 5, dd = (idx & 31) << 1;
        __nv_bfloat162 h2 = __floats2bfloat162_rn(tile[dd * 129 + n], tile[(dd + 1) * 129 + n]);
        *reinterpret_cast<__nv_bfloat162*>(
            &dstH[(size_t)(nb * 128 + n) * DDIM + dc * 64 + dd]) = h2;
    }
    if (which && tid < 128) {
        float s = 0.f;
        #pragma unroll 8
        for (int d = 0; d < 64; d++) { float v = tile[d * 129 + tid]; s += v * v; }
        g_nrm_part[dc][nb * 128 + tid] = s;
    }
}

__global__ void vq_norm_combine() {
    int k = blockIdx.x * 256 + threadIdx.x;
    float s = 0.f;
    #pragma unroll
    for (int i = 0; i < 16; i++) s += g_nrm_part[i][k];
    g_cbnorm[k] = s;
}

// ---------------------------------------------------------------------------
// coarse GEMM: 128 tokens x 256 codes x K=1024 (32-dim chunks), double-buffered
// cp.async (2 x 24KB = 48KB static smem). 256 threads = 8 warps (2 M x 4 N),
// warp tile 64x64. Epilogue: fp16 d2 + per-token block min.
// ---------------------------------------------------------------------------
#define STG_B 24576     // A 8KB + B 16KB per stage

__global__ __launch_bounds__(256, 1) void vq_gemm() {
    __shared__ __align__(1024) char sm[2 * STG_B];
    const uint32_t smb = smem_u32(sm);
    const int tid = threadIdx.x, wid = tid >> 5, lane = tid & 31;
    const int warp_m = wid & 1, warp_n = wid >> 1;
    const int t0 = blockIdx.x * 128, k0 = blockIdx.y * 256;
    const char* zp = (const char*)g_Zh + (size_t)t0 * DDIM * 2;
    const char* cp = (const char*)g_CBh + (size_t)k0 * DDIM * 2;

    float acc[4][8][4];
    #pragma unroll
    for (int i = 0; i < 4; i++)
        #pragma unroll
        for (int j = 0; j < 8; j++)
            #pragma unroll
            for (int q = 0; q < 4; q++) acc[i][j][q] = 0.f;

    // stage loader: A 512 + B 1024 granules of 16B -> 6 cp.async / thread
    auto load_stage = [&](int stg, int kc) {
        const uint32_t sbase = smb + stg * STG_B;
        #pragma unroll
        for (int u = 0; u < 6; u++) {
            int i = tid + u * 256;
            bool isB = i >= 512;
            int j = isB ? i - 512 : i;
            int r = j >> 2, c = j & 3;
            uint32_t dst = sw_addr(sbase + (isB ? 8192 : 0), r, c);
            const char* src = (isB ? cp : zp) + (size_t)r * 2048 + kc * 64 + c * 16;
            cp_async16(dst, src);
        }
        cp_commit();
    };

    load_stage(0, 0);

    for (int kc = 0; kc < 32; kc++) {
        cp_wait0();                 // stage kc resident
        __syncthreads();            // all compute on the other buffer finished
        if (kc + 1 < 32) load_stage((kc + 1) & 1, kc + 1);

        const uint32_t sA = smb + (kc & 1) * STG_B;
        const uint32_t sB = sA + 8192;
        #pragma unroll
        for (int s = 0; s < 2; s++) {
            uint32_t a[4][4], b[4][4];
            #pragma unroll
            for (int mt = 0; mt < 4; mt++) {
                int row = warp_m * 64 + mt * 16 + ((lane >> 3) & 1) * 8 + (lane & 7);
                int kg = s * 2 + (lane >> 4);
                ldsm4(a[mt], sw_addr(sA, row, kg));
            }
            #pragma unroll
            for (int np = 0; np < 4; np++) {
                int row = warp_n * 64 + np * 16 + ((lane >> 4) << 3) + (lane & 7);
                int kg = s * 2 + ((lane >> 3) & 1);
                ldsm4(b[np], sw_addr(sB, row, kg));
            }
            #pragma unroll
            for (int mt = 0; mt < 4; mt++) {
                #pragma unroll
                for (int np = 0; np < 4; np++) {
                    mma16816(acc[mt][np * 2 + 0], a[mt], b[np][0], b[np][1]);
                    mma16816(acc[mt][np * 2 + 1], a[mt], b[np][2], b[np][3]);
                }
            }
        }
    }
    __syncthreads();

    // ---- epilogue ----
    const int kbase = k0 + warp_n * 64 + (lane & 3) * 2;
    float2 cbn[8];
    #pragma unroll
    for (int nt = 0; nt < 8; nt++)
        cbn[nt] = *reinterpret_cast<const float2*>(&g_cbnorm[kbase + nt * 8]);

    unsigned long long* smin = reinterpret_cast<unsigned long long*>(sm);  // 128*4 u64

    #pragma unroll
    for (int mt = 0; mt < 4; mt++) {
        #pragma unroll
        for (int half = 0; half < 2; half++) {
            const int tl = warp_m * 64 + mt * 16 + half * 8 + (lane >> 2);
            __half* drow = g_d2h + (size_t)(t0 + tl) * NTOK;
            unsigned long long best = ~0ull;
            #pragma unroll
            for (int nt = 0; nt < 8; nt++) {
                float dx = fmaf(-2.f, acc[mt][nt][half * 2 + 0], cbn[nt].x);
                float dy = fmaf(-2.f, acc[mt][nt][half * 2 + 1], cbn[nt].y);
                *reinterpret_cast<__half2*>(&drow[kbase + nt * 8]) = __floats2half2_rn(dx, dy);
                unsigned long long p0 =
                    ((unsigned long long)order_f32(dx) << 32) | (unsigned)(kbase + nt * 8);
                unsigned long long p1 =
                    ((unsigned long long)order_f32(dy) << 32) | (unsigned)(kbase + nt * 8 + 1);
                if (p0 < best) best = p0;
                if (p1 < best) best = p1;
            }
            // reduce over the 4 lanes sharing this t (lane&3)
            {
                unsigned long long v = __shfl_xor_sync(0xFFFFFFFFu, best, 1);
                if (v < best) best = v;
                v = __shfl_xor_sync(0xFFFFFFFFu, best, 2);
                if (v < best) best = v;
            }
            if ((lane & 3) == 0) smin[tl * 4 + warp_n] = best;
        }
    }
    __syncthreads();
    if (tid < 128) {
        unsigned long long b = smin[tid * 4];
        #pragma unroll
        for (int i = 1; i < 4; i++)
            if (smin[tid * 4 + i] < b) b = smin[tid * 4 + i];
        atomicMin(&g_best[t0 + tid], b);
        g_blockmin[(t0 + tid) * KBLK + blockIdx.y] = unorder_f32((unsigned)(b >> 32));
    }
}

// ---------------------------------------------------------------------------
// collect: warp per token; only scan 256-code segments whose blockmin < thr.
// ---------------------------------------------------------------------------
__global__ void vq_collect() {
    const int w = threadIdx.x >> 5, lane = threadIdx.x & 31;
    const int t = blockIdx.x * 8 + w;
    const float thr = unorder_f32((unsigned)(g_best[t] >> 32)) + MARGIN;
    const float* bm = g_blockmin + (size_t)t * KBLK;
    for (int b = 0; b < KBLK; b++) {
        if (bm[b] >= thr) continue;
        const __half2* p = (const __half2*)(g_d2h + (size_t)t * NTOK + b * 256);
        #pragma unroll
        for (int u = 0; u < 4; u++) {
            __half2 v = p[lane * 4 + u];
            float x = __low2float(v), y = __high2float(v);
            int kb = b * 256 + (lane * 4 + u) * 2;
            if (x < thr) {
                unsigned pos = atomicAdd(&g_ncand, 1u);
                if (pos < CAP_CAND) g_cand[pos] = ((unsigned)t << 12) | (unsigned)kb;
            }
            if (y < thr) {
                unsigned pos = atomicAdd(&g_ncand, 1u);
                if (pos < CAP_CAND) g_cand[pos] = ((unsigned)t << 12) | (unsigned)(kb + 1);
            }
        }
    }
}

// ---------------------------------------------------------------------------
// rescore: exact fp32 dot per candidate (one warp each) -> g_final
// ---------------------------------------------------------------------------
__global__ void vq_rescore() {
    const int wg = blockIdx.x * 4 + (threadIdx.x >> 5);
    const int lane = threadIdx.x & 31;
    unsigned cnt = g_ncand; if (cnt > CAP_CAND) cnt = CAP_CAND;
    for (unsigned c = wg; c < cnt; c += gridDim.x * 4) {
        unsigned e = g_cand[c];
        int n = e >> 12, k = e & 4095;
        const float4* za = (const float4*)(g_Zt  + (size_t)n * DDIM);
        const float4* cb = (const float4*)(g_CBt + (size_t)k * DDIM);
        float s = 0.f;
        #pragma unroll
        for (int j = 0; j < 8; j++) {
            float4 a = za[j * 32 + lane], b = cb[j * 32 + lane];
            s = fmaf(a.x, b.x, s); s = fmaf(a.y, b.y, s);
            s = fmaf(a.z, b.z, s); s = fmaf(a.w, b.w, s);
        }
        #pragma unroll
        for (int o = 16; o; o >>= 1) s += __shfl_xor_sync(0xFFFFFFFFu, s, o);
        if (lane == 0) {
            float d2 = fmaf(-2.f, s, g_cbnorm[k]);
            unsigned long long pk = ((unsigned long long)order_f32(d2) << 32) | (unsigned)k;
            atomicMin(&g_final[n], pk);
        }
    }
}

// ---------------------------------------------------------------------------
// gather: contiguous reads of token-major g_CBt + smem transpose.
// grid (32 nb, 16 dc), 256 threads; block = 128 tokens x 64 dims.
// ---------------------------------------------------------------------------
__global__ void vq_gather(const float* __restrict__ Z, float* __restrict__ out, int writeQ) {
    __shared__ float qs[128][65];
    __shared__ int ks[128];
    const int nb = blockIdx.x, dc = blockIdx.y, tid = threadIdx.x;
    if (tid < 128) ks[tid] = (int)(g_final[nb * 128 + tid] & 0xFFFFFFFFu);
    __syncthreads();
    for (int idx = tid; idx < 128 * 64; idx += 256) {
        int n = idx >> 6, d = idx & 63;
        qs[n][d] = g_CBt[(size_t)ks[n] * DDIM + dc * 64 + d];
    }
    __syncthreads();
    float* out_q = out + (size_t)DDIM * NTOK;
    for (int idx = tid; idx < 64 * 128; idx += 256) {
        int d = idx >> 7, n = idx & 127;
        int gd = dc * 64 + d, gn = nb * 128 + n;
        float q = qs[n][d];
        float z = Z[(size_t)gd * NTOK + gn];
        out[(size_t)gd * NTOK + gn] = q + (z - q);
        if (writeQ) out_q[(size_t)gd * NTOK + gn] = q;
    }
}

// ---------------------------------------------------------------------------
extern "C" void kernel_launch(void* const* d_in, const int* in_sizes, int n_in,
                              void* d_out, int out_size) {
    const float* Z  = (const float*)d_in[0];
    const float* CB = (const float*)d_in[1];
    float* out = (float*)d_out;
    const int writeQ = (out_size >= 2 * DDIM * NTOK) ? 1 : 0;

    vq_init<<<16, 256>>>();
    vq_prep<<<dim3(32, 16, 2), 256>>>(Z, CB);
    vq_norm_combine<<<16, 256>>>();
    vq_gemm<<<dim3(32, 16), 256>>>();
    vq_collect<<<512, 256>>>();
    vq_rescore<<<512, 128>>>();
    vq_gather<<<dim3(32, 16), 256>>>(Z, out, writeQ);
}

// round 7
// speedup vs baseline: 1.1760x; 1.1759x over previous
#include <cuda_runtime.h>
#include <cuda_bf16.h>
#include <cuda_fp16.h>
#include <cstdint>

// VQ-VAE nearest-codebook quantization.
//   idx[n] = argmin_k (||cb_k||^2 - 2 z_n . cb_k);  zq = cb[idx];  z_st = zq + (z - zq)
// Coarse: bf16 mma.sync GEMM -> fp16 d2 + per-128-code block minima.
// Rescue: all k with coarse d2 < coarse_min + MARGIN get exact fp32 rescore.

#define NTOK 4096
#define DDIM 1024
#define CAP_CAND (1 << 18)
#define MARGIN 3.0f
#define KBLK 32           // 4096 / 128 code-blocks

__device__ unsigned long long g_best[NTOK];     // coarse packed (ord(d2)<<32)|k
__device__ unsigned long long g_final[NTOK];    // exact packed
__device__ float g_cbnorm[NTOK];
__device__ float g_nrm_part[16][NTOK];
__device__ float g_blockmin[NTOK * KBLK];       // coarse min per (token, 128-code block)
__device__ float g_Zt[(size_t)NTOK * DDIM];     // fp32 token-major (rescore)
__device__ float g_CBt[(size_t)NTOK * DDIM];
__device__ __align__(16) __nv_bfloat16 g_Zh[(size_t)NTOK * DDIM];
__device__ __align__(16) __nv_bfloat16 g_CBh[(size_t)NTOK * DDIM];
__device__ __half g_d2h[(size_t)NTOK * NTOK];   // coarse d2 [token][code], fp16
__device__ unsigned g_cand[CAP_CAND];
__device__ unsigned g_ncand;

// ---- helpers ----
__device__ __forceinline__ uint32_t smem_u32(const void* p) {
    uint32_t a;
    asm("{ .reg .u64 t; cvta.to.shared.u64 t, %1; cvt.u32.u64 %0, t; }" : "=r"(a) : "l"(p));
    return a;
}
__device__ __forceinline__ unsigned order_f32(float f) {
    unsigned u = __float_as_uint(f);
    return (u & 0x80000000u) ? ~u : (u | 0x80000000u);
}
__device__ __forceinline__ float unorder_f32(unsigned u) {
    return (u & 0x80000000u) ? __uint_as_float(u ^ 0x80000000u) : __uint_as_float(~u);
}
__device__ __forceinline__ void cp_async16(uint32_t dst, const void* src) {
    asm volatile("cp.async.cg.shared.global [%0], [%1], 16;" :: "r"(dst), "l"(src));
}
__device__ __forceinline__ void cp_commit() { asm volatile("cp.async.commit_group;"); }
__device__ __forceinline__ void cp_wait1()  { asm volatile("cp.async.wait_group 1;"); }
__device__ __forceinline__ void ldsm4(uint32_t (&r)[4], uint32_t addr) {
    asm volatile("ldmatrix.sync.aligned.m8n8.x4.shared.b16 {%0,%1,%2,%3}, [%4];"
                 : "=r"(r[0]), "=r"(r[1]), "=r"(r[2]), "=r"(r[3]) : "r"(addr));
}
__device__ __forceinline__ void mma16816(float (&c)[4], const uint32_t (&a)[4],
                                         uint32_t b0, uint32_t b1) {
    asm volatile(
        "mma.sync.aligned.m16n8k16.row.col.f32.bf16.bf16.f32 "
        "{%0,%1,%2,%3}, {%4,%5,%6,%7}, {%8,%9}, {%0,%1,%2,%3};"
        : "+f"(c[0]), "+f"(c[1]), "+f"(c[2]), "+f"(c[3])
        : "r"(a[0]), "r"(a[1]), "r"(a[2]), "r"(a[3]), "r"(b0), "r"(b1));
}
// Swizzled smem tile: rows x 4 k-granules of 16B; 2 rows per 128B line,
// xor over ((row>>1)&7) -> conflict-free for cp.async stores and ldmatrix.
__device__ __forceinline__ uint32_t sw_addr(uint32_t base, int row, int kg) {
    return base + ((row >> 1) << 7) + ((((kg + ((row & 1) << 2)) ^ ((row >> 1) & 7))) << 4);
}

// ---------------------------------------------------------------------------
// prep: token-major fp32 + bf16 row-major + partial cb norms (fixed order)
// grid (32 nb, 16 dc, 2 which), 256 threads. Block = 128 cols x 64 dims.
// ---------------------------------------------------------------------------
__global__ void vq_prep(const float* __restrict__ Z, const float* __restrict__ CB) {
    __shared__ float tile[64 * 129];
    const int nb = blockIdx.x, dc = blockIdx.y, which = blockIdx.z;
    const float* src = which ? CB : Z;
    float* dstT = which ? g_CBt : g_Zt;
    __nv_bfloat16* dstH = which ? g_CBh : g_Zh;
    const int tid = threadIdx.x;

    for (int idx = tid; idx < 64 * 128; idx += 256) {
        int d = idx >> 7, n = idx & 127;
        tile[d * 129 + n] = src[(size_t)(dc * 64 + d) * NTOK + nb * 128 + n];
    }
    __syncthreads();
    for (int idx = tid; idx < 64 * 128; idx += 256) {
        int n = idx >> 6, d = idx & 63;
        dstT[(size_t)(nb * 128 + n) * DDIM + dc * 64 + d] = tile[d * 129 + n];
    }
    for (int idx = tid; idx < 64 * 64; idx += 256) {
        int n = idx >> 5, dd = (idx & 31) << 1;
        __nv_bfloat162 h2 = __floats2bfloat162_rn(tile[dd * 129 + n], tile[(dd + 1) * 129 + n]);
        *reinterpret_cast<__nv_bfloat162*>(
            &dstH[(size_t)(nb * 128 + n) * DDIM + dc * 64 + dd]) = h2;
    }
    if (which && tid < 128) {
        float s = 0.f;
        #pragma unroll 8
        for (int d = 0; d < 64; d++) { float v = tile[d * 129 + tid]; s += v * v; }
        g_nrm_part[dc][nb * 128 + tid] = s;
    }
}

// combine norms + init bests/counters (runs after prep, before gemm)
__global__ void vq_norm_combine() {
    int k = blockIdx.x * 256 + threadIdx.x;
    float s = 0.f;
    #pragma unroll
    for (int i = 0; i < 16; i++) s += g_nrm_part[i][k];
    g_cbnorm[k] = s;
    g_best[k] = ~0ull;
    g_final[k] = ~0ull;
    if (k == 0) g_ncand = 0;
}

// ---------------------------------------------------------------------------
// coarse GEMM: 128 tokens x 128 codes x K=1024 (32-dim chunks), 3-stage
// cp.async (3 x 16KB = 48KB static smem). 256 threads = 8 warps (2 M x 4 N),
// warp tile 64x32. regs ~126 -> 2 CTAs/SM.
// Epilogue: fp16 d2 + per-token 128-code block min.
// ---------------------------------------------------------------------------
#define STG_B 16384     // A 8KB + B 8KB per stage

__global__ __launch_bounds__(256, 2) void vq_gemm() {
    __shared__ __align__(1024) char sm[3 * STG_B];
    const uint32_t smb = smem_u32(sm);
    const int tid = threadIdx.x, wid = tid >> 5, lane = tid & 31;
    const int warp_m = wid & 1, warp_n = wid >> 1;
    const int t0 = blockIdx.x * 128, k0 = blockIdx.y * 128;
    const char* zp = (const char*)g_Zh + (size_t)t0 * DDIM * 2;
    const char* cp = (const char*)g_CBh + (size_t)k0 * DDIM * 2;

    float acc[4][4][4];
    #pragma unroll
    for (int i = 0; i < 4; i++)
        #pragma unroll
        for (int j = 0; j < 4; j++)
            #pragma unroll
            for (int q = 0; q < 4; q++) acc[i][j][q] = 0.f;

    // stage loader: 1024 granules of 16B (A rows 0..127, then B rows 0..127)
    auto load_stage = [&](int stg, int kc) {
        const uint32_t sbase = smb + stg * STG_B;
        #pragma unroll
        for (int u = 0; u < 4; u++) {
            int i = tid + u * 256;
            int r = (i >> 2) & 127;
            int c = i & 3;
            bool isB = i >= 512;
            uint32_t dst = sw_addr(sbase + (isB ? 8192 : 0), r, c);
            const char* src = (isB ? cp : zp) + (size_t)r * 2048 + kc * 64 + c * 16;
            cp_async16(dst, src);
        }
        cp_commit();
    };

    load_stage(0, 0);
    load_stage(1, 1);

    for (int kc = 0; kc < 32; kc++) {
        cp_wait1();
        __syncthreads();
        if (kc + 2 < 32) load_stage((kc + 2) % 3, kc + 2);
        else cp_commit();     // empty group keeps wait_group 1 covering stage kc

        const uint32_t sA = smb + (kc % 3) * STG_B;
        const uint32_t sB = sA + 8192;
        #pragma unroll
        for (int s = 0; s < 2; s++) {
            uint32_t a[4][4], b[2][4];
            #pragma unroll
            for (int mt = 0; mt < 4; mt++) {
                int row = warp_m * 64 + mt * 16 + ((lane >> 3) & 1) * 8 + (lane & 7);
                int kg = s * 2 + (lane >> 4);
                ldsm4(a[mt], sw_addr(sA, row, kg));
            }
            #pragma unroll
            for (int np = 0; np < 2; np++) {
                int row = warp_n * 32 + np * 16 + ((lane >> 4) << 3) + (lane & 7);
                int kg = s * 2 + ((lane >> 3) & 1);
                ldsm4(b[np], sw_addr(sB, row, kg));
            }
            #pragma unroll
            for (int mt = 0; mt < 4; mt++) {
                #pragma unroll
                for (int np = 0; np < 2; np++) {
                    mma16816(acc[mt][np * 2 + 0], a[mt], b[np][0], b[np][1]);
                    mma16816(acc[mt][np * 2 + 1], a[mt], b[np][2], b[np][3]);
                }
            }
        }
        __syncthreads();
    }

    // ---- epilogue: d2 = cbnorm[k] - 2*dot -> fp16 store + block minima ----
    const int kbase = k0 + warp_n * 32 + (lane & 3) * 2;
    float2 cbn[4];
    #pragma unroll
    for (int nt = 0; nt < 4; nt++)
        cbn[nt] = *reinterpret_cast<const float2*>(&g_cbnorm[kbase + nt * 8]);

    unsigned long long* smin = reinterpret_cast<unsigned long long*>(sm);  // 128*4 u64

    #pragma unroll
    for (int mt = 0; mt < 4; mt++) {
        #pragma unroll
        for (int half = 0; half < 2; half++) {
            const int tl = warp_m * 64 + mt * 16 + half * 8 + (lane >> 2);
            __half* drow = g_d2h + (size_t)(t0 + tl) * NTOK;
            unsigned long long best = ~0ull;
            #pragma unroll
            for (int nt = 0; nt < 4; nt++) {
                float dx = fmaf(-2.f, acc[mt][nt][half * 2 + 0], cbn[nt].x);
                float dy = fmaf(-2.f, acc[mt][nt][half * 2 + 1], cbn[nt].y);
                *reinterpret_cast<__half2*>(&drow[kbase + nt * 8]) = __floats2half2_rn(dx, dy);
                unsigned long long p0 =
                    ((unsigned long long)order_f32(dx) << 32) | (unsigned)(kbase + nt * 8);
                unsigned long long p1 =
                    ((unsigned long long)order_f32(dy) << 32) | (unsigned)(kbase + nt * 8 + 1);
                if (p0 < best) best = p0;
                if (p1 < best) best = p1;
            }
            // reduce over the 4 lanes sharing this token row (lane&3 varies)
            {
                unsigned long long v = __shfl_xor_sync(0xFFFFFFFFu, best, 1);
                if (v < best) best = v;
                v = __shfl_xor_sync(0xFFFFFFFFu, best, 2);
                if (v < best) best = v;
            }
            if ((lane & 3) == 0) smin[tl * 4 + warp_n] = best;
        }
    }
    __syncthreads();
    if (tid < 128) {
        unsigned long long b = smin[tid * 4];
        #pragma unroll
        for (int i = 1; i < 4; i++)
            if (smin[tid * 4 + i] < b) b = smin[tid * 4 + i];
        atomicMin(&g_best[t0 + tid], b);
        g_blockmin[(t0 + tid) * KBLK + blockIdx.y] = unorder_f32((unsigned)(b >> 32));
    }
}

// ---------------------------------------------------------------------------
// collect: warp per token; only scan 128-code segments whose blockmin < thr.
// ---------------------------------------------------------------------------
__global__ void vq_collect() {
    const int w = threadIdx.x >> 5, lane = threadIdx.x & 31;
    const int t = blockIdx.x * 8 + w;
    const float thr = unorder_f32((unsigned)(g_best[t] >> 32)) + MARGIN;
    const float* bm = g_blockmin + (size_t)t * KBLK;
    for (int b = 0; b < KBLK; b++) {
        if (bm[b] >= thr) continue;
        const __half2* p = (const __half2*)(g_d2h + (size_t)t * NTOK + b * 128);
        #pragma unroll
        for (int u = 0; u < 2; u++) {
            __half2 v = p[lane * 2 + u];
            float x = __low2float(v), y = __high2float(v);
            int kb = b * 128 + (lane * 2 + u) * 2;
            if (x < thr) {
                unsigned pos = atomicAdd(&g_ncand, 1u);
                if (pos < CAP_CAND) g_cand[pos] = ((unsigned)t << 12) | (unsigned)kb;
            }
            if (y < thr) {
                unsigned pos = atomicAdd(&g_ncand, 1u);
                if (pos < CAP_CAND) g_cand[pos] = ((unsigned)t << 12) | (unsigned)(kb + 1);
            }
        }
    }
}

// ---------------------------------------------------------------------------
// rescore: exact fp32 dot per candidate (one warp each) -> g_final
// ---------------------------------------------------------------------------
__global__ void vq_rescore() {
    const int wg = blockIdx.x * 4 + (threadIdx.x >> 5);
    const int lane = threadIdx.x & 31;
    unsigned cnt = g_ncand; if (cnt > CAP_CAND) cnt = CAP_CAND;
    for (unsigned c = wg; c < cnt; c += gridDim.x * 4) {
        unsigned e = g_cand[c];
        int n = e >> 12, k = e & 4095;
        const float4* za = (const float4*)(g_Zt  + (size_t)n * DDIM);
        const float4* cb = (const float4*)(g_CBt + (size_t)k * DDIM);
        float s = 0.f;
        #pragma unroll
        for (int j = 0; j < 8; j++) {
            float4 a = za[j * 32 + lane], b = cb[j * 32 + lane];
            s = fmaf(a.x, b.x, s); s = fmaf(a.y, b.y, s);
            s = fmaf(a.z, b.z, s); s = fmaf(a.w, b.w, s);
        }
        #pragma unroll
        for (int o = 16; o; o >>= 1) s += __shfl_xor_sync(0xFFFFFFFFu, s, o);
        if (lane == 0) {
            float d2 = fmaf(-2.f, s, g_cbnorm[k]);
            unsigned long long pk = ((unsigned long long)order_f32(d2) << 32) | (unsigned)k;
            atomicMin(&g_final[n], pk);
        }
    }
}

// ---------------------------------------------------------------------------
// gather: contiguous reads of token-major g_CBt + smem transpose.
// grid (32 nb, 16 dc), 256 threads; block = 128 tokens x 64 dims.
// ---------------------------------------------------------------------------
__global__ void vq_gather(const float* __restrict__ Z, float* __restrict__ out, int writeQ) {
    __shared__ float qs[128][65];
    __shared__ int ks[128];
    const int nb = blockIdx.x, dc = blockIdx.y, tid = threadIdx.x;
    if (tid < 128) ks[tid] = (int)(g_final[nb * 128 + tid] & 0xFFFFFFFFu);
    __syncthreads();
    for (int idx = tid; idx < 128 * 64; idx += 256) {
        int n = idx >> 6, d = idx & 63;
        qs[n][d] = g_CBt[(size_t)ks[n] * DDIM + dc * 64 + d];
    }
    __syncthreads();
    float* out_q = out + (size_t)DDIM * NTOK;
    for (int idx = tid; idx < 64 * 128; idx += 256) {
        int d = idx >> 7, n = idx & 127;
        int gd = dc * 64 + d, gn = nb * 128 + n;
        float q = qs[n][d];
        float z = Z[(size_t)gd * NTOK + gn];
        out[(size_t)gd * NTOK + gn] = q + (z - q);
        if (writeQ) out_q[(size_t)gd * NTOK + gn] = q;
    }
}

// ---------------------------------------------------------------------------
extern "C" void kernel_launch(void* const* d_in, const int* in_sizes, int n_in,
                              void* d_out, int out_size) {
    const float* Z  = (const float*)d_in[0];
    const float* CB = (const float*)d_in[1];
    float* out = (float*)d_out;
    const int writeQ = (out_size >= 2 * DDIM * NTOK) ? 1 : 0;

    vq_prep<<<dim3(32, 16, 2), 256>>>(Z, CB);
    vq_norm_combine<<<16, 256>>>();
    vq_gemm<<<dim3(32, 32), 256>>>();
    vq_collect<<<512, 256>>>();
    vq_rescore<<<512, 128>>>();
    vq_gather<<<dim3(32, 16), 256>>>(Z, out, writeQ);
}

// round 8
// speedup vs baseline: 1.1934x; 1.0147x over previous
#include <cuda_runtime.h>
#include <cuda_bf16.h>
#include <cuda_fp16.h>
#include <cstdint>

// VQ-VAE nearest-codebook quantization.
//   idx[n] = argmin_k (||cb_k||^2 - 2 z_n . cb_k);  zq = cb[idx];  z_st = zq + (z - zq)
// Coarse: bf16 mma.sync GEMM -> fp16 d2 + per-128-code block minima.
// Refine: warp/token; candidates with coarse d2 < min + MARGIN; if >1, exact
// fp32 rescore picks the argmin (tie -> lowest k, matching jnp.argmin).

#define NTOK 4096
#define DDIM 1024
#define MARGIN 3.0f
#define KBLK 32           // 4096 / 128 code-blocks

__device__ unsigned long long g_best[NTOK];     // coarse packed (ord(d2)<<32)|k
__device__ unsigned long long g_final[NTOK];    // chosen k (low 32 bits)
__device__ float g_cbnorm[NTOK];
__device__ float g_nrm_part[16][NTOK];
__device__ float g_blockmin[NTOK * KBLK];       // coarse min per (token, 128-code block)
__device__ float g_Zt[(size_t)NTOK * DDIM];     // fp32 token-major (rescore)
__device__ float g_CBt[(size_t)NTOK * DDIM];
__device__ __align__(16) __nv_bfloat16 g_Zh[(size_t)NTOK * DDIM];
__device__ __align__(16) __nv_bfloat16 g_CBh[(size_t)NTOK * DDIM];
__device__ __half g_d2h[(size_t)NTOK * NTOK];   // coarse d2 [token][code], fp16

// ---- helpers ----
__device__ __forceinline__ uint32_t smem_u32(const void* p) {
    uint32_t a;
    asm("{ .reg .u64 t; cvta.to.shared.u64 t, %1; cvt.u32.u64 %0, t; }" : "=r"(a) : "l"(p));
    return a;
}
__device__ __forceinline__ unsigned order_f32(float f) {
    unsigned u = __float_as_uint(f);
    return (u & 0x80000000u) ? ~u : (u | 0x80000000u);
}
__device__ __forceinline__ float unorder_f32(unsigned u) {
    return (u & 0x80000000u) ? __uint_as_float(u ^ 0x80000000u) : __uint_as_float(~u);
}
__device__ __forceinline__ void cp_async16(uint32_t dst, const void* src) {
    asm volatile("cp.async.cg.shared.global [%0], [%1], 16;" :: "r"(dst), "l"(src));
}
__device__ __forceinline__ void cp_commit() { asm volatile("cp.async.commit_group;"); }
__device__ __forceinline__ void cp_wait1()  { asm volatile("cp.async.wait_group 1;"); }
__device__ __forceinline__ void ldsm4(uint32_t (&r)[4], uint32_t addr) {
    asm volatile("ldmatrix.sync.aligned.m8n8.x4.shared.b16 {%0,%1,%2,%3}, [%4];"
                 : "=r"(r[0]), "=r"(r[1]), "=r"(r[2]), "=r"(r[3]) : "r"(addr));
}
__device__ __forceinline__ void mma16816(float (&c)[4], const uint32_t (&a)[4],
                                         uint32_t b0, uint32_t b1) {
    asm volatile(
        "mma.sync.aligned.m16n8k16.row.col.f32.bf16.bf16.f32 "
        "{%0,%1,%2,%3}, {%4,%5,%6,%7}, {%8,%9}, {%0,%1,%2,%3};"
        : "+f"(c[0]), "+f"(c[1]), "+f"(c[2]), "+f"(c[3])
        : "r"(a[0]), "r"(a[1]), "r"(a[2]), "r"(a[3]), "r"(b0), "r"(b1));
}
// Swizzled smem tile: rows x 4 k-granules of 16B; 2 rows per 128B line,
// xor over ((row>>1)&7) -> conflict-free for cp.async stores and ldmatrix.
__device__ __forceinline__ uint32_t sw_addr(uint32_t base, int row, int kg) {
    return base + ((row >> 1) << 7) + ((((kg + ((row & 1) << 2)) ^ ((row >> 1) & 7))) << 4);
}

// ---------------------------------------------------------------------------
// prep: token-major fp32 + bf16 row-major + partial cb norms (fixed order)
// grid (32 nb, 16 dc, 2 which), 256 threads. Block = 128 cols x 64 dims.
// ---------------------------------------------------------------------------
__global__ void vq_prep(const float* __restrict__ Z, const float* __restrict__ CB) {
    __shared__ float tile[64 * 129];
    const int nb = blockIdx.x, dc = blockIdx.y, which = blockIdx.z;
    const float* src = which ? CB : Z;
    float* dstT = which ? g_CBt : g_Zt;
    __nv_bfloat16* dstH = which ? g_CBh : g_Zh;
    const int tid = threadIdx.x;

    for (int idx = tid; idx < 64 * 128; idx += 256) {
        int d = idx >> 7, n = idx & 127;
        tile[d * 129 + n] = src[(size_t)(dc * 64 + d) * NTOK + nb * 128 + n];
    }
    __syncthreads();
    for (int idx = tid; idx < 64 * 128; idx += 256) {
        int n = idx >> 6, d = idx & 63;
        dstT[(size_t)(nb * 128 + n) * DDIM + dc * 64 + d] = tile[d * 129 + n];
    }
    for (int idx = tid; idx < 64 * 64; idx += 256) {
        int n = idx >> 5, dd = (idx & 31) << 1;
        __nv_bfloat162 h2 = __floats2bfloat162_rn(tile[dd * 129 + n], tile[(dd + 1) * 129 + n]);
        *reinterpret_cast<__nv_bfloat162*>(
            &dstH[(size_t)(nb * 128 + n) * DDIM + dc * 64 + dd]) = h2;
    }
    if (which && tid < 128) {
        float s = 0.f;
        #pragma unroll 8
        for (int d = 0; d < 64; d++) { float v = tile[d * 129 + tid]; s += v * v; }
        g_nrm_part[dc][nb * 128 + tid] = s;
    }
}

// combine norms + init coarse bests (after prep, before gemm)
__global__ void vq_norm_combine() {
    int k = blockIdx.x * 256 + threadIdx.x;
    float s = 0.f;
    #pragma unroll
    for (int i = 0; i < 16; i++) s += g_nrm_part[i][k];
    g_cbnorm[k] = s;
    g_best[k] = ~0ull;
}

// ---------------------------------------------------------------------------
// coarse GEMM: 128 tokens x 128 codes x K=1024 (32-dim chunks), 3-stage
// cp.async (48KB static smem). 256 threads = 8 warps (2 M x 4 N),
// warp tile 64x32, 2 CTAs/SM. Epilogue: fp16 d2 + per-token block min.
// ---------------------------------------------------------------------------
#define STG_B 16384     // A 8KB + B 8KB per stage

__global__ __launch_bounds__(256, 2) void vq_gemm() {
    __shared__ __align__(1024) char sm[3 * STG_B];
    const uint32_t smb = smem_u32(sm);
    const int tid = threadIdx.x, wid = tid >> 5, lane = tid & 31;
    const int warp_m = wid & 1, warp_n = wid >> 1;
    const int t0 = blockIdx.x * 128, k0 = blockIdx.y * 128;
    const char* zp = (const char*)g_Zh + (size_t)t0 * DDIM * 2;
    const char* cp = (const char*)g_CBh + (size_t)k0 * DDIM * 2;

    float acc[4][4][4];
    #pragma unroll
    for (int i = 0; i < 4; i++)
        #pragma unroll
        for (int j = 0; j < 4; j++)
            #pragma unroll
            for (int q = 0; q < 4; q++) acc[i][j][q] = 0.f;

    auto load_stage = [&](int stg, int kc) {
        const uint32_t sbase = smb + stg * STG_B;
        #pragma unroll
        for (int u = 0; u < 4; u++) {
            int i = tid + u * 256;
            int r = (i >> 2) & 127;
            int c = i & 3;
            bool isB = i >= 512;
            uint32_t dst = sw_addr(sbase + (isB ? 8192 : 0), r, c);
            const char* src = (isB ? cp : zp) + (size_t)r * 2048 + kc * 64 + c * 16;
            cp_async16(dst, src);
        }
        cp_commit();
    };

    load_stage(0, 0);
    load_stage(1, 1);

    for (int kc = 0; kc < 32; kc++) {
        cp_wait1();
        __syncthreads();
        if (kc + 2 < 32) load_stage((kc + 2) % 3, kc + 2);
        else cp_commit();     // empty group keeps wait_group 1 covering stage kc

        const uint32_t sA = smb + (kc % 3) * STG_B;
        const uint32_t sB = sA + 8192;
        #pragma unroll
        for (int s = 0; s < 2; s++) {
            uint32_t a[4][4], b[2][4];
            #pragma unroll
            for (int mt = 0; mt < 4; mt++) {
                int row = warp_m * 64 + mt * 16 + ((lane >> 3) & 1) * 8 + (lane & 7);
                int kg = s * 2 + (lane >> 4);
                ldsm4(a[mt], sw_addr(sA, row, kg));
            }
            #pragma unroll
            for (int np = 0; np < 2; np++) {
                int row = warp_n * 32 + np * 16 + ((lane >> 4) << 3) + (lane & 7);
                int kg = s * 2 + ((lane >> 3) & 1);
                ldsm4(b[np], sw_addr(sB, row, kg));
            }
            #pragma unroll
            for (int mt = 0; mt < 4; mt++) {
                #pragma unroll
                for (int np = 0; np < 2; np++) {
                    mma16816(acc[mt][np * 2 + 0], a[mt], b[np][0], b[np][1]);
                    mma16816(acc[mt][np * 2 + 1], a[mt], b[np][2], b[np][3]);
                }
            }
        }
        __syncthreads();
    }

    // ---- epilogue: d2 = cbnorm[k] - 2*dot -> fp16 store + block minima ----
    const int kbase = k0 + warp_n * 32 + (lane & 3) * 2;
    float2 cbn[4];
    #pragma unroll
    for (int nt = 0; nt < 4; nt++)
        cbn[nt] = *reinterpret_cast<const float2*>(&g_cbnorm[kbase + nt * 8]);

    unsigned long long* smin = reinterpret_cast<unsigned long long*>(sm);

    #pragma unroll
    for (int mt = 0; mt < 4; mt++) {
        #pragma unroll
        for (int half = 0; half < 2; half++) {
            const int tl = warp_m * 64 + mt * 16 + half * 8 + (lane >> 2);
            __half* drow = g_d2h + (size_t)(t0 + tl) * NTOK;
            unsigned long long best = ~0ull;
            #pragma unroll
            for (int nt = 0; nt < 4; nt++) {
                float dx = fmaf(-2.f, acc[mt][nt][half * 2 + 0], cbn[nt].x);
                float dy = fmaf(-2.f, acc[mt][nt][half * 2 + 1], cbn[nt].y);
                *reinterpret_cast<__half2*>(&drow[kbase + nt * 8]) = __floats2half2_rn(dx, dy);
                unsigned long long p0 =
                    ((unsigned long long)order_f32(dx) << 32) | (unsigned)(kbase + nt * 8);
                unsigned long long p1 =
                    ((unsigned long long)order_f32(dy) << 32) | (unsigned)(kbase + nt * 8 + 1);
                if (p0 < best) best = p0;
                if (p1 < best) best = p1;
            }
            {
                unsigned long long v = __shfl_xor_sync(0xFFFFFFFFu, best, 1);
                if (v < best) best = v;
                v = __shfl_xor_sync(0xFFFFFFFFu, best, 2);
                if (v < best) best = v;
            }
            if ((lane & 3) == 0) smin[tl * 4 + warp_n] = best;
        }
    }
    __syncthreads();
    if (tid < 128) {
        unsigned long long b = smin[tid * 4];
        #pragma unroll
        for (int i = 1; i < 4; i++)
            if (smin[tid * 4 + i] < b) b = smin[tid * 4 + i];
        atomicMin(&g_best[t0 + tid], b);
        g_blockmin[(t0 + tid) * KBLK + blockIdx.y] = unorder_f32((unsigned)(b >> 32));
    }
}

// ---------------------------------------------------------------------------
// refine (fused collect + rescore): warp per token, no atomics.
//  - lanes hold the 32 block minima; ballot -> qualifying blocks
//  - pre-pass counts candidates; 1 candidate => it IS the argmin (margin proof)
//  - else: cache z row in regs, exact fp32 dot per candidate, min packed
// ---------------------------------------------------------------------------
__global__ __launch_bounds__(256) void vq_refine() {
    const int w = threadIdx.x >> 5, lane = threadIdx.x & 31;
    const int t = blockIdx.x * 8 + w;
    const float thr = unorder_f32((unsigned)(g_best[t] >> 32)) + MARGIN;

    const float bmv = g_blockmin[t * KBLK + lane];
    unsigned qmask = __ballot_sync(0xFFFFFFFFu, bmv < thr);
    const __half* drow = g_d2h + (size_t)t * NTOK;

    // pre-pass: count candidates, remember the single one if unique
    int total = 0;
    int only_k = -1;
    for (unsigned qm = qmask; qm; qm &= qm - 1) {
        int b = __ffs(qm) - 1;
        float2 vv = *reinterpret_cast<const float2*>(&drow[b * 128 + lane * 4]);  // 2x half2
        __half2 h0 = reinterpret_cast<__half2&>(vv.x);
        __half2 h1 = reinterpret_cast<__half2&>(vv.y);
        float v[4] = { __low2float(h0), __high2float(h0), __low2float(h1), __high2float(h1) };
        #pragma unroll
        for (int s = 0; s < 4; s++) {
            unsigned m = __ballot_sync(0xFFFFFFFFu, v[s] < thr);
            if (m && total == 0) only_k = b * 128 + (__ffs(m) - 1) * 4 + s;
            total += __popc(m);
        }
    }
    if (total <= 1) {
        if (lane == 0) g_final[t] = (unsigned long long)(unsigned)only_k;
        return;
    }

    // multi-candidate: cache z row, rescore each candidate exactly
    const float4* za = (const float4*)(g_Zt + (size_t)t * DDIM);
    float4 zr[8];
    #pragma unroll
    for (int j = 0; j < 8; j++) zr[j] = za[j * 32 + lane];

    unsigned long long bestpk = ~0ull;
    for (unsigned qm = qmask; qm; qm &= qm - 1) {
        int b = __ffs(qm) - 1;
        float2 vv = *reinterpret_cast<const float2*>(&drow[b * 128 + lane * 4]);
        __half2 h0 = reinterpret_cast<__half2&>(vv.x);
        __half2 h1 = reinterpret_cast<__half2&>(vv.y);
        float v[4] = { __low2float(h0), __high2float(h0), __low2float(h1), __high2float(h1) };
        #pragma unroll
        for (int s = 0; s < 4; s++) {
            unsigned m = __ballot_sync(0xFFFFFFFFu, v[s] < thr);
            while (m) {
                int src = __ffs(m) - 1;
                m &= m - 1;
                int k = b * 128 + src * 4 + s;
                const float4* cb = (const float4*)(g_CBt + (size_t)k * DDIM);
                float sdot = 0.f;
                #pragma unroll
                for (int j = 0; j < 8; j++) {
                    float4 a = zr[j], bb = cb[j * 32 + lane];
                    sdot = fmaf(a.x, bb.x, sdot); sdot = fmaf(a.y, bb.y, sdot);
                    sdot = fmaf(a.z, bb.z, sdot); sdot = fmaf(a.w, bb.w, sdot);
                }
                #pragma unroll
                for (int o = 16; o; o >>= 1) sdot += __shfl_xor_sync(0xFFFFFFFFu, sdot, o);
                float d2 = fmaf(-2.f, sdot, g_cbnorm[k]);
                unsigned long long pk =
                    ((unsigned long long)order_f32(d2) << 32) | (unsigned)k;
                if (pk < bestpk) bestpk = pk;
            }
        }
    }
    if (lane == 0) g_final[t] = bestpk & 0xFFFFFFFFull;
}

// ---------------------------------------------------------------------------
// gather: contiguous reads of token-major g_CBt + smem transpose.
// grid (32 nb, 16 dc), 256 threads; block = 128 tokens x 64 dims.
// ---------------------------------------------------------------------------
__global__ void vq_gather(const float* __restrict__ Z, float* __restrict__ out, int writeQ) {
    __shared__ float qs[128][65];
    __shared__ int ks[128];
    const int nb = blockIdx.x, dc = blockIdx.y, tid = threadIdx.x;
    if (tid < 128) ks[tid] = (int)(g_final[nb * 128 + tid] & 0xFFFFFFFFu);
    __syncthreads();
    for (int idx = tid; idx < 128 * 64; idx += 256) {
        int n = idx >> 6, d = idx & 63;
        qs[n][d] = g_CBt[(size_t)ks[n] * DDIM + dc * 64 + d];
    }
    __syncthreads();
    float* out_q = out + (size_t)DDIM * NTOK;
    for (int idx = tid; idx < 64 * 128; idx += 256) {
        int d = idx >> 7, n = idx & 127;
        int gd = dc * 64 + d, gn = nb * 128 + n;
        float q = qs[n][d];
        float z = Z[(size_t)gd * NTOK + gn];
        out[(size_t)gd * NTOK + gn] = q + (z - q);
        if (writeQ) out_q[(size_t)gd * NTOK + gn] = q;
    }
}

// ---------------------------------------------------------------------------
extern "C" void kernel_launch(void* const* d_in, const int* in_sizes, int n_in,
                              void* d_out, int out_size) {
    const float* Z  = (const float*)d_in[0];
    const float* CB = (const float*)d_in[1];
    float* out = (float*)d_out;
    const int writeQ = (out_size >= 2 * DDIM * NTOK) ? 1 : 0;

    vq_prep<<<dim3(32, 16, 2), 256>>>(Z, CB);
    vq_norm_combine<<<16, 256>>>();
    vq_gemm<<<dim3(32, 32), 256>>>();
    vq_refine<<<512, 256>>>();
    vq_gather<<<dim3(32, 16), 256>>>(Z, out, writeQ);
}

// round 9
// speedup vs baseline: 1.2312x; 1.0317x over previous
#include <cuda_runtime.h>
#include <cuda_bf16.h>
#include <cuda_fp16.h>
#include <cstdint>

// VQ-VAE nearest-codebook quantization.
//   idx[n] = argmin_k (||cb_k||^2 - 2 z_n . cb_k);  zq = cb[idx];  z_st = zq + (z - zq)
// Coarse: bf16 mma.sync GEMM -> fp16 d2 + per-128-code block minima.
// Refine: block-balanced; candidates with coarse d2 < min + MARGIN; if >1 for a
// token, exact fp32 rescore picks the argmin (tie -> lowest k, = jnp.argmin).

#define NTOK 4096
#define DDIM 1024
#define MARGIN 3.0f
#define KBLK 32           // 4096 / 128 code-blocks
#define WCAP 2048         // worklist capacity per refine block (8 tokens)

__device__ unsigned long long g_best[NTOK];     // coarse packed (ord(d2)<<32)|k
__device__ unsigned long long g_final[NTOK];    // chosen k (low 32 bits)
__device__ float g_cbnorm[NTOK];
__device__ float g_nrm_part[16][NTOK];
__device__ float g_blockmin[NTOK * KBLK];       // coarse min per (token, 128-code block)
__device__ float g_Zt[(size_t)NTOK * DDIM];     // fp32 token-major (rescore)
__device__ float g_CBt[(size_t)NTOK * DDIM];
__device__ __align__(16) __nv_bfloat16 g_Zh[(size_t)NTOK * DDIM];
__device__ __align__(16) __nv_bfloat16 g_CBh[(size_t)NTOK * DDIM];
__device__ __half g_d2h[(size_t)NTOK * NTOK];   // coarse d2 [token][code], fp16

// ---- helpers ----
__device__ __forceinline__ uint32_t smem_u32(const void* p) {
    uint32_t a;
    asm("{ .reg .u64 t; cvta.to.shared.u64 t, %1; cvt.u32.u64 %0, t; }" : "=r"(a) : "l"(p));
    return a;
}
__device__ __forceinline__ unsigned order_f32(float f) {
    unsigned u = __float_as_uint(f);
    return (u & 0x80000000u) ? ~u : (u | 0x80000000u);
}
__device__ __forceinline__ float unorder_f32(unsigned u) {
    return (u & 0x80000000u) ? __uint_as_float(u ^ 0x80000000u) : __uint_as_float(~u);
}
__device__ __forceinline__ void cp_async16(uint32_t dst, const void* src) {
    asm volatile("cp.async.cg.shared.global [%0], [%1], 16;" :: "r"(dst), "l"(src));
}
__device__ __forceinline__ void cp_commit() { asm volatile("cp.async.commit_group;"); }
__device__ __forceinline__ void cp_wait1()  { asm volatile("cp.async.wait_group 1;"); }
__device__ __forceinline__ void ldsm4(uint32_t (&r)[4], uint32_t addr) {
    asm volatile("ldmatrix.sync.aligned.m8n8.x4.shared.b16 {%0,%1,%2,%3}, [%4];"
                 : "=r"(r[0]), "=r"(r[1]), "=r"(r[2]), "=r"(r[3]) : "r"(addr));
}
__device__ __forceinline__ void mma16816(float (&c)[4], const uint32_t (&a)[4],
                                         uint32_t b0, uint32_t b1) {
    asm volatile(
        "mma.sync.aligned.m16n8k16.row.col.f32.bf16.bf16.f32 "
        "{%0,%1,%2,%3}, {%4,%5,%6,%7}, {%8,%9}, {%0,%1,%2,%3};"
        : "+f"(c[0]), "+f"(c[1]), "+f"(c[2]), "+f"(c[3])
        : "r"(a[0]), "r"(a[1]), "r"(a[2]), "r"(a[3]), "r"(b0), "r"(b1));
}
// Swizzled smem tile: rows x 4 k-granules of 16B; 2 rows per 128B line,
// xor over ((row>>1)&7) -> conflict-free for cp.async stores and ldmatrix.
__device__ __forceinline__ uint32_t sw_addr(uint32_t base, int row, int kg) {
    return base + ((row >> 1) << 7) + ((((kg + ((row & 1) << 2)) ^ ((row >> 1) & 7))) << 4);
}

// ---------------------------------------------------------------------------
// prep: token-major fp32 + bf16 row-major + partial cb norms (fixed order)
// grid (32 nb, 16 dc, 2 which), 256 threads. Block = 128 cols x 64 dims.
// ---------------------------------------------------------------------------
__global__ void vq_prep(const float* __restrict__ Z, const float* __restrict__ CB) {
    __shared__ float tile[64 * 129];
    const int nb = blockIdx.x, dc = blockIdx.y, which = blockIdx.z;
    const float* src = which ? CB : Z;
    float* dstT = which ? g_CBt : g_Zt;
    __nv_bfloat16* dstH = which ? g_CBh : g_Zh;
    const int tid = threadIdx.x;

    for (int idx = tid; idx < 64 * 128; idx += 256) {
        int d = idx >> 7, n = idx & 127;
        tile[d * 129 + n] = src[(size_t)(dc * 64 + d) * NTOK + nb * 128 + n];
    }
    __syncthreads();
    for (int idx = tid; idx < 64 * 128; idx += 256) {
        int n = idx >> 6, d = idx & 63;
        dstT[(size_t)(nb * 128 + n) * DDIM + dc * 64 + d] = tile[d * 129 + n];
    }
    for (int idx = tid; idx < 64 * 64; idx += 256) {
        int n = idx >> 5, dd = (idx & 31) << 1;
        __nv_bfloat162 h2 = __floats2bfloat162_rn(tile[dd * 129 + n], tile[(dd + 1) * 129 + n]);
        *reinterpret_cast<__nv_bfloat162*>(
            &dstH[(size_t)(nb * 128 + n) * DDIM + dc * 64 + dd]) = h2;
    }
    if (which && tid < 128) {
        float s = 0.f;
        #pragma unroll 8
        for (int d = 0; d < 64; d++) { float v = tile[d * 129 + tid]; s += v * v; }
        g_nrm_part[dc][nb * 128 + tid] = s;
    }
}

// combine norms + init coarse bests (after prep, before gemm)
__global__ void vq_norm_combine() {
    int k = blockIdx.x * 256 + threadIdx.x;
    float s = 0.f;
    #pragma unroll
    for (int i = 0; i < 16; i++) s += g_nrm_part[i][k];
    g_cbnorm[k] = s;
    g_best[k] = ~0ull;
}

// ---------------------------------------------------------------------------
// coarse GEMM: 128 tokens x 128 codes x K=1024 (32-dim chunks), 3-stage
// cp.async (48KB static smem). 256 threads = 8 warps (2 M x 4 N),
// warp tile 64x32, 2 CTAs/SM. ONE sync per chunk (3-stage ring makes the
// trailing barrier redundant). Epilogue: fp16 d2 + per-token block min.
// ---------------------------------------------------------------------------
#define STG_B 16384     // A 8KB + B 8KB per stage

__global__ __launch_bounds__(256, 2) void vq_gemm() {
    __shared__ __align__(1024) char sm[3 * STG_B];
    const uint32_t smb = smem_u32(sm);
    const int tid = threadIdx.x, wid = tid >> 5, lane = tid & 31;
    const int warp_m = wid & 1, warp_n = wid >> 1;
    const int t0 = blockIdx.x * 128, k0 = blockIdx.y * 128;
    const char* zp = (const char*)g_Zh + (size_t)t0 * DDIM * 2;
    const char* cp = (const char*)g_CBh + (size_t)k0 * DDIM * 2;

    float acc[4][4][4];
    #pragma unroll
    for (int i = 0; i < 4; i++)
        #pragma unroll
        for (int j = 0; j < 4; j++)
            #pragma unroll
            for (int q = 0; q < 4; q++) acc[i][j][q] = 0.f;

    auto load_stage = [&](int stg, int kc) {
        const uint32_t sbase = smb + stg * STG_B;
        #pragma unroll
        for (int u = 0; u < 4; u++) {
            int i = tid + u * 256;
            int r = (i >> 2) & 127;
            int c = i & 3;
            bool isB = i >= 512;
            uint32_t dst = sw_addr(sbase + (isB ? 8192 : 0), r, c);
            const char* src = (isB ? cp : zp) + (size_t)r * 2048 + kc * 64 + c * 16;
            cp_async16(dst, src);
        }
        cp_commit();
    };

    load_stage(0, 0);
    load_stage(1, 1);

    for (int kc = 0; kc < 32; kc++) {
        cp_wait1();              // stage kc resident (own thread's ops)
        __syncthreads();         // all threads' stores visible; prior compute done
        if (kc + 2 < 32) load_stage((kc + 2) % 3, kc + 2);
        else cp_commit();        // empty group keeps wait_group 1 aligned

        const uint32_t sA = smb + (kc % 3) * STG_B;
        const uint32_t sB = sA + 8192;
        #pragma unroll
        for (int s = 0; s < 2; s++) {
            uint32_t a[4][4], b[2][4];
            #pragma unroll
            for (int mt = 0; mt < 4; mt++) {
                int row = warp_m * 64 + mt * 16 + ((lane >> 3) & 1) * 8 + (lane & 7);
                int kg = s * 2 + (lane >> 4);
                ldsm4(a[mt], sw_addr(sA, row, kg));
            }
            #pragma unroll
            for (int np = 0; np < 2; np++) {
                int row = warp_n * 32 + np * 16 + ((lane >> 4) << 3) + (lane & 7);
                int kg = s * 2 + ((lane >> 3) & 1);
                ldsm4(b[np], sw_addr(sB, row, kg));
            }
            #pragma unroll
            for (int mt = 0; mt < 4; mt++) {
                #pragma unroll
                for (int np = 0; np < 2; np++) {
                    mma16816(acc[mt][np * 2 + 0], a[mt], b[np][0], b[np][1]);
                    mma16816(acc[mt][np * 2 + 1], a[mt], b[np][2], b[np][3]);
                }
            }
        }
    }

    // ---- epilogue: d2 = cbnorm[k] - 2*dot -> fp16 store + block minima ----
    // (smin uses stage-0 bytes; last loop iteration reads stage 2 -> disjoint)
    const int kbase = k0 + warp_n * 32 + (lane & 3) * 2;
    float2 cbn[4];
    #pragma unroll
    for (int nt = 0; nt < 4; nt++)
        cbn[nt] = *reinterpret_cast<const float2*>(&g_cbnorm[kbase + nt * 8]);

    unsigned long long* smin = reinterpret_cast<unsigned long long*>(sm);

    #pragma unroll
    for (int mt = 0; mt < 4; mt++) {
        #pragma unroll
        for (int half = 0; half < 2; half++) {
            const int tl = warp_m * 64 + mt * 16 + half * 8 + (lane >> 2);
            __half* drow = g_d2h + (size_t)(t0 + tl) * NTOK;
            unsigned long long best = ~0ull;
            #pragma unroll
            for (int nt = 0; nt < 4; nt++) {
                float dx = fmaf(-2.f, acc[mt][nt][half * 2 + 0], cbn[nt].x);
                float dy = fmaf(-2.f, acc[mt][nt][half * 2 + 1], cbn[nt].y);
                *reinterpret_cast<__half2*>(&drow[kbase + nt * 8]) = __floats2half2_rn(dx, dy);
                unsigned long long p0 =
                    ((unsigned long long)order_f32(dx) << 32) | (unsigned)(kbase + nt * 8);
                unsigned long long p1 =
                    ((unsigned long long)order_f32(dy) << 32) | (unsigned)(kbase + nt * 8 + 1);
                if (p0 < best) best = p0;
                if (p1 < best) best = p1;
            }
            {
                unsigned long long v = __shfl_xor_sync(0xFFFFFFFFu, best, 1);
                if (v < best) best = v;
                v = __shfl_xor_sync(0xFFFFFFFFu, best, 2);
                if (v < best) best = v;
            }
            if ((lane & 3) == 0) smin[tl * 4 + warp_n] = best;
        }
    }
    __syncthreads();
    if (tid < 128) {
        unsigned long long b = smin[tid * 4];
        #pragma unroll
        for (int i = 1; i < 4; i++)
            if (smin[tid * 4 + i] < b) b = smin[tid * 4 + i];
        atomicMin(&g_best[t0 + tid], b);
        g_blockmin[(t0 + tid) * KBLK + blockIdx.y] = unorder_f32((unsigned)(b >> 32));
    }
}

// ---------------------------------------------------------------------------
// refine: block = 8 tokens, 8 warps. Phase A: each warp classifies its token,
// pushing all candidates (coarse d2 < min + MARGIN) into a shared worklist.
// Phase B: all warps drain the worklist (exact fp32 dot, smem atomicMin).
// Tokens with a single candidate skip rescore (margin proof: it IS the argmin).
// ---------------------------------------------------------------------------
__global__ __launch_bounds__(256) void vq_refine() {
    __shared__ unsigned s_work[WCAP];            // (tslot<<12) | k
    __shared__ int s_nwork;
    __shared__ int s_cnt[8];
    __shared__ int s_first[8];
    __shared__ unsigned long long s_min[8];
    const int w = threadIdx.x >> 5, lane = threadIdx.x & 31;
    const int t0 = blockIdx.x * 8;
    const int t = t0 + w;

    if (threadIdx.x == 0) s_nwork = 0;
    if (threadIdx.x < 8) s_min[threadIdx.x] = ~0ull;
    __syncthreads();

    const float thr = unorder_f32((unsigned)(g_best[t] >> 32)) + MARGIN;
    const float bmv = g_blockmin[t * KBLK + lane];
    unsigned qmask = __ballot_sync(0xFFFFFFFFu, bmv < thr);
    const __half* drow = g_d2h + (size_t)t * NTOK;

    int total = 0, first_k = -1;
    for (unsigned qm = qmask; qm; qm &= qm - 1) {
        int b = __ffs(qm) - 1;
        float2 vv = *reinterpret_cast<const float2*>(&drow[b * 128 + lane * 4]);
        __half2 h0 = reinterpret_cast<__half2&>(vv.x);
        __half2 h1 = reinterpret_cast<__half2&>(vv.y);
        float v[4] = { __low2float(h0), __high2float(h0), __low2float(h1), __high2float(h1) };
        #pragma unroll
        for (int s = 0; s < 4; s++) {
            unsigned m = __ballot_sync(0xFFFFFFFFu, v[s] < thr);
            if (!m) continue;
            int ldr = __ffs(m) - 1;
            if (total == 0) first_k = b * 128 + ldr * 4 + s;
            unsigned base = 0;
            if (lane == ldr) base = (unsigned)atomicAdd(&s_nwork, __popc(m));
            base = __shfl_sync(0xFFFFFFFFu, base, ldr);
            if (m & (1u << lane)) {
                unsigned pos = base + (unsigned)__popc(m & ((1u << lane) - 1));
                if (pos < WCAP)
                    s_work[pos] = ((unsigned)w << 12) | (unsigned)(b * 128 + lane * 4 + s);
            }
            total += __popc(m);
        }
    }
    if (lane == 0) { s_cnt[w] = total; s_first[w] = first_k; }
    __syncthreads();

    // Phase B: block-wide rescore of all worklist entries (skip unique tokens)
    int nwork = s_nwork; if (nwork > WCAP) nwork = WCAP;
    for (int e = w; e < nwork; e += 8) {
        unsigned ent = s_work[e];
        int tslot = ent >> 12, k = ent & 4095;
        if (s_cnt[tslot] <= 1) continue;
        const float4* za = (const float4*)(g_Zt + (size_t)(t0 + tslot) * DDIM);
        const float4* cb = (const float4*)(g_CBt + (size_t)k * DDIM);
        float sdot = 0.f;
        #pragma unroll
        for (int j = 0; j < 8; j++) {
            float4 a = za[j * 32 + lane], bb = cb[j * 32 + lane];
            sdot = fmaf(a.x, bb.x, sdot); sdot = fmaf(a.y, bb.y, sdot);
            sdot = fmaf(a.z, bb.z, sdot); sdot = fmaf(a.w, bb.w, sdot);
        }
        #pragma unroll
        for (int o = 16; o; o >>= 1) sdot += __shfl_xor_sync(0xFFFFFFFFu, sdot, o);
        if (lane == 0) {
            float d2 = fmaf(-2.f, sdot, g_cbnorm[k]);
            unsigned long long pk = ((unsigned long long)order_f32(d2) << 32) | (unsigned)k;
            atomicMin(&s_min[tslot], pk);
        }
    }
    __syncthreads();
    if (threadIdx.x < 8) {
        int ts = threadIdx.x;
        unsigned kk = (s_cnt[ts] <= 1) ? (unsigned)s_first[ts]
                                       : (unsigned)(s_min[ts] & 0xFFFFFFFFull);
        g_final[t0 + ts] = (unsigned long long)kk;
    }
}

// ---------------------------------------------------------------------------
// gather: contiguous reads of token-major g_CBt + smem transpose.
// grid (32 nb, 16 dc), 256 threads; block = 128 tokens x 64 dims.
// ---------------------------------------------------------------------------
__global__ void vq_gather(const float* __restrict__ Z, float* __restrict__ out, int writeQ) {
    __shared__ float qs[128][65];
    __shared__ int ks[128];
    const int nb = blockIdx.x, dc = blockIdx.y, tid = threadIdx.x;
    if (tid < 128) ks[tid] = (int)(g_final[nb * 128 + tid] & 0xFFFFFFFFu);
    __syncthreads();
    for (int idx = tid; idx < 128 * 64; idx += 256) {
        int n = idx >> 6, d = idx & 63;
        qs[n][d] = g_CBt[(size_t)ks[n] * DDIM + dc * 64 + d];
    }
    __syncthreads();
    float* out_q = out + (size_t)DDIM * NTOK;
    for (int idx = tid; idx < 64 * 128; idx += 256) {
        int d = idx >> 7, n = idx & 127;
        int gd = dc * 64 + d, gn = nb * 128 + n;
        float q = qs[n][d];
        float z = Z[(size_t)gd * NTOK + gn];
        out[(size_t)gd * NTOK + gn] = q + (z - q);
        if (writeQ) out_q[(size_t)gd * NTOK + gn] = q;
    }
}

// ---------------------------------------------------------------------------
extern "C" void kernel_launch(void* const* d_in, const int* in_sizes, int n_in,
                              void* d_out, int out_size) {
    const float* Z  = (const float*)d_in[0];
    const float* CB = (const float*)d_in[1];
    float* out = (float*)d_out;
    const int writeQ = (out_size >= 2 * DDIM * NTOK) ? 1 : 0;

    vq_prep<<<dim3(32, 16, 2), 256>>>(Z, CB);
    vq_norm_combine<<<16, 256>>>();
    vq_gemm<<<dim3(32, 32), 256>>>();
    vq_refine<<<512, 256>>>();
    vq_gather<<<dim3(32, 16), 256>>>(Z, out, writeQ);
}

// round 12
// speedup vs baseline: 1.2645x; 1.0271x over previous
#include <cuda_runtime.h>
#include <cuda_bf16.h>
#include <cuda_fp16.h>
#include <cstdint>

// VQ-VAE nearest-codebook quantization.
//   idx[n] = argmin_k (||cb_k||^2 - 2 z_n . cb_k);  zq = cb[idx];  z_st = zq + (z - zq)
// Coarse: bf16 mma.sync GEMM -> fp16 d2 + per-128-code block minima.
// Refine: block-balanced; candidates with coarse d2 < min + MARGIN; if >1 for a
// token, exact fp32 rescore picks the argmin (tie -> lowest k, = jnp.argmin).

#define NTOK 4096
#define DDIM 1024
#define MARGIN 3.0f
#define KBLK 32           // 4096 / 128 code-blocks
#define WCAP 2048         // worklist capacity per refine block (8 tokens)

__device__ unsigned long long g_best[NTOK];     // coarse packed (ord(d2)<<32)|k
__device__ unsigned long long g_final[NTOK];    // chosen k (low 32 bits)
__device__ float g_cbnorm[NTOK];
__device__ float g_nrm_part[16][NTOK];
__device__ float g_blockmin[NTOK * KBLK];       // coarse min per (token, 128-code block)
__device__ float g_Zt[(size_t)NTOK * DDIM];     // fp32 token-major (rescore)
__device__ float g_CBt[(size_t)NTOK * DDIM];
__device__ __align__(16) __nv_bfloat16 g_Zh[(size_t)NTOK * DDIM];
__device__ __align__(16) __nv_bfloat16 g_CBh[(size_t)NTOK * DDIM];
__device__ __half g_d2h[(size_t)NTOK * NTOK];   // coarse d2 [token][code], fp16

// ---- helpers ----
__device__ __forceinline__ uint32_t smem_u32(const void* p) {
    uint32_t a;
    asm("{ .reg .u64 t; cvta.to.shared.u64 t, %1; cvt.u32.u64 %0, t; }" : "=r"(a) : "l"(p));
    return a;
}
__device__ __forceinline__ unsigned order_f32(float f) {
    unsigned u = __float_as_uint(f);
    return (u & 0x80000000u) ? ~u : (u | 0x80000000u);
}
__device__ __forceinline__ float unorder_f32(unsigned u) {
    return (u & 0x80000000u) ? __uint_as_float(u ^ 0x80000000u) : __uint_as_float(~u);
}
__device__ __forceinline__ void cp_async16(uint32_t dst, const void* src) {
    asm volatile("cp.async.cg.shared.global [%0], [%1], 16;" :: "r"(dst), "l"(src));
}
__device__ __forceinline__ void cp_commit() { asm volatile("cp.async.commit_group;"); }
__device__ __forceinline__ void cp_wait1()  { asm volatile("cp.async.wait_group 1;"); }
__device__ __forceinline__ void ldsm4(uint32_t (&r)[4], uint32_t addr) {
    asm volatile("ldmatrix.sync.aligned.m8n8.x4.shared.b16 {%0,%1,%2,%3}, [%4];"
                 : "=r"(r[0]), "=r"(r[1]), "=r"(r[2]), "=r"(r[3]) : "r"(addr));
}
__device__ __forceinline__ void mma16816(float (&c)[4], const uint32_t (&a)[4],
                                         uint32_t b0, uint32_t b1) {
    asm volatile(
        "mma.sync.aligned.m16n8k16.row.col.f32.bf16.bf16.f32 "
        "{%0,%1,%2,%3}, {%4,%5,%6,%7}, {%8,%9}, {%0,%1,%2,%3};"
        : "+f"(c[0]), "+f"(c[1]), "+f"(c[2]), "+f"(c[3])
        : "r"(a[0]), "r"(a[1]), "r"(a[2]), "r"(a[3]), "r"(b0), "r"(b1));
}
// Swizzled smem tile: rows x 4 k-granules of 16B; 2 rows per 128B line,
// xor over ((row>>1)&7) -> conflict-free for cp.async stores and ldmatrix.
__device__ __forceinline__ uint32_t sw_addr(uint32_t base, int row, int kg) {
    return base + ((row >> 1) << 7) + ((((kg + ((row & 1) << 2)) ^ ((row >> 1) & 7))) << 4);
}

// ---------------------------------------------------------------------------
// prep: token-major fp32 + bf16 row-major + partial cb norms (fixed order)
// grid (32 nb, 16 dc, 2 which), 256 threads. Block = 128 cols x 64 dims.
// ---------------------------------------------------------------------------
__global__ void vq_prep(const float* __restrict__ Z, const float* __restrict__ CB) {
    __shared__ float tile[64 * 129];
    const int nb = blockIdx.x, dc = blockIdx.y, which = blockIdx.z;
    const float* src = which ? CB : Z;
    float* dstT = which ? g_CBt : g_Zt;
    __nv_bfloat16* dstH = which ? g_CBh : g_Zh;
    const int tid = threadIdx.x;

    for (int idx = tid; idx < 64 * 128; idx += 256) {
        int d = idx >> 7, n = idx & 127;
        tile[d * 129 + n] = src[(size_t)(dc * 64 + d) * NTOK + nb * 128 + n];
    }
    __syncthreads();
    for (int idx = tid; idx < 64 * 128; idx += 256) {
        int n = idx >> 6, d = idx & 63;
        dstT[(size_t)(nb * 128 + n) * DDIM + dc * 64 + d] = tile[d * 129 + n];
    }
    for (int idx = tid; idx < 64 * 64; idx += 256) {
        int n = idx >> 5, dd = (idx & 31) << 1;
        __nv_bfloat162 h2 = __floats2bfloat162_rn(tile[dd * 129 + n], tile[(dd + 1) * 129 + n]);
        *reinterpret_cast<__nv_bfloat162*>(
            &dstH[(size_t)(nb * 128 + n) * DDIM + dc * 64 + dd]) = h2;
    }
    if (which && tid < 128) {
        float s = 0.f;
        #pragma unroll 8
        for (int d = 0; d < 64; d++) { float v = tile[d * 129 + tid]; s += v * v; }
        g_nrm_part[dc][nb * 128 + tid] = s;
    }
}

// combine norms + init coarse bests (after prep, before gemm)
__global__ void vq_norm_combine() {
    int k = blockIdx.x * 256 + threadIdx.x;
    float s = 0.f;
    #pragma unroll
    for (int i = 0; i < 16; i++) s += g_nrm_part[i][k];
    g_cbnorm[k] = s;
    g_best[k] = ~0ull;
}

// ---------------------------------------------------------------------------
// coarse GEMM: 128 tokens x 128 codes x K=1024 (32-dim chunks), 3-stage
// cp.async (48KB static smem). 128 threads = 4 warps (2 M x 2 N),
// warp tile 64x64, 2 CTAs/SM. smem traffic/chunk/SM: 96KB < 128B/cyc*1024 ->
// tensor-bound, not crossbar-bound. One sync per chunk (3-stage ring).
// Epilogue: fp16 d2 + per-token block min.
// ---------------------------------------------------------------------------
#define STG_B 16384     // A 8KB + B 8KB per stage

__global__ __launch_bounds__(128, 2) void vq_gemm() {
    __shared__ __align__(1024) char sm[3 * STG_B];
    const uint32_t smb = smem_u32(sm);
    const int tid = threadIdx.x, wid = tid >> 5, lane = tid & 31;
    const int warp_m = wid & 1, warp_n = wid >> 1;       // 2 x 2
    const int t0 = blockIdx.x * 128, k0 = blockIdx.y * 128;
    const char* zp = (const char*)g_Zh + (size_t)t0 * DDIM * 2;
    const char* cp = (const char*)g_CBh + (size_t)k0 * DDIM * 2;

    float acc[4][8][4];
    #pragma unroll
    for (int i = 0; i < 4; i++)
        #pragma unroll
        for (int j = 0; j < 8; j++)
            #pragma unroll
            for (int q = 0; q < 4; q++) acc[i][j][q] = 0.f;

    // stage loader: 1024 granules of 16B, 8 per thread
    auto load_stage = [&](int stg, int kc) {
        const uint32_t sbase = smb + stg * STG_B;
        #pragma unroll
        for (int u = 0; u < 8; u++) {
            int i = tid + u * 128;
            int r = (i >> 2) & 127;
            int c = i & 3;
            bool isB = i >= 512;
            uint32_t dst = sw_addr(sbase + (isB ? 8192 : 0), r, c);
            const char* src = (isB ? cp : zp) + (size_t)r * 2048 + kc * 64 + c * 16;
            cp_async16(dst, src);
        }
        cp_commit();
    };

    load_stage(0, 0);
    load_stage(1, 1);

    for (int kc = 0; kc < 32; kc++) {
        cp_wait1();              // stage kc resident (own thread's ops)
        __syncthreads();         // all threads' stores visible; ring slot free
        if (kc + 2 < 32) load_stage((kc + 2) % 3, kc + 2);
        else cp_commit();        // empty group keeps wait_group 1 aligned

        const uint32_t sA = smb + (kc % 3) * STG_B;
        const uint32_t sB = sA + 8192;
        #pragma unroll
        for (int s = 0; s < 2; s++) {
            uint32_t a[4][4], b[4][4];
            #pragma unroll
            for (int mt = 0; mt < 4; mt++) {
                int row = warp_m * 64 + mt * 16 + ((lane >> 3) & 1) * 8 + (lane & 7);
                int kg = s * 2 + (lane >> 4);
                ldsm4(a[mt], sw_addr(sA, row, kg));
            }
            #pragma unroll
            for (int np = 0; np < 4; np++) {
                int row = warp_n * 64 + np * 16 + ((lane >> 4) << 3) + (lane & 7);
                int kg = s * 2 + ((lane >> 3) & 1);
                ldsm4(b[np], sw_addr(sB, row, kg));
            }
            #pragma unroll
            for (int mt = 0; mt < 4; mt++) {
                #pragma unroll
                for (int np = 0; np < 4; np++) {
                    mma16816(acc[mt][np * 2 + 0], a[mt], b[np][0], b[np][1]);
                    mma16816(acc[mt][np * 2 + 1], a[mt], b[np][2], b[np][3]);
                }
            }
        }
    }

    // ---- epilogue: d2 = cbnorm[k] - 2*dot -> fp16 store + block minima ----
    const int kbase = k0 + warp_n * 64 + (lane & 3) * 2;
    float2 cbn[8];
    #pragma unroll
    for (int nt = 0; nt < 8; nt++)
        cbn[nt] = *reinterpret_cast<const float2*>(&g_cbnorm[kbase + nt * 8]);

    unsigned long long* smin = reinterpret_cast<unsigned long long*>(sm);  // 128*2 u64

    #pragma unroll
    for (int mt = 0; mt < 4; mt++) {
        #pragma unroll
        for (int half = 0; half < 2; half++) {
            const int tl = warp_m * 64 + mt * 16 + half * 8 + (lane >> 2);
            __half* drow = g_d2h + (size_t)(t0 + tl) * NTOK;
            unsigned long long best = ~0ull;
            #pragma unroll
            for (int nt = 0; nt < 8; nt++) {
                float dx = fmaf(-2.f, acc[mt][nt][half * 2 + 0], cbn[nt].x);
                float dy = fmaf(-2.f, acc[mt][nt][half * 2 + 1], cbn[nt].y);
                *reinterpret_cast<__half2*>(&drow[kbase + nt * 8]) = __floats2half2_rn(dx, dy);
                unsigned long long p0 =
                    ((unsigned long long)order_f32(dx) << 32) | (unsigned)(kbase + nt * 8);
                unsigned long long p1 =
                    ((unsigned long long)order_f32(dy) << 32) | (unsigned)(kbase + nt * 8 + 1);
                if (p0 < best) best = p0;
                if (p1 < best) best = p1;
            }
            {
                unsigned long long v = __shfl_xor_sync(0xFFFFFFFFu, best, 1);
                if (v < best) best = v;
                v = __shfl_xor_sync(0xFFFFFFFFu, best, 2);
                if (v < best) best = v;
            }
            if ((lane & 3) == 0) smin[tl * 2 + warp_n] = best;
        }
    }
    __syncthreads();
    if (tid < 128) {
        unsigned long long b = smin[tid * 2];
        if (smin[tid * 2 + 1] < b) b = smin[tid * 2 + 1];
        atomicMin(&g_best[t0 + tid], b);
        g_blockmin[(t0 + tid) * KBLK + blockIdx.y] = unorder_f32((unsigned)(b >> 32));
    }
}

// ---------------------------------------------------------------------------
// refine: block = 8 tokens, 8 warps. Phase A: each warp classifies its token,
// pushing all candidates (coarse d2 < min + MARGIN) into a shared worklist.
// Phase B: all warps drain the worklist (exact fp32 dot, smem atomicMin).
// Tokens with a single candidate skip rescore (margin proof: it IS the argmin).
// ---------------------------------------------------------------------------
__global__ __launch_bounds__(256) void vq_refine() {
    __shared__ unsigned s_work[WCAP];            // (tslot<<12) | k
    __shared__ int s_nwork;
    __shared__ int s_cnt[8];
    __shared__ int s_first[8];
    __shared__ unsigned long long s_min[8];
    const int w = threadIdx.x >> 5, lane = threadIdx.x & 31;
    const int t0 = blockIdx.x * 8;
    const int t = t0 + w;

    if (threadIdx.x == 0) s_nwork = 0;
    if (threadIdx.x < 8) s_min[threadIdx.x] = ~0ull;
    __syncthreads();

    const float thr = unorder_f32((unsigned)(g_best[t] >> 32)) + MARGIN;
    const float bmv = g_blockmin[t * KBLK + lane];
    unsigned qmask = __ballot_sync(0xFFFFFFFFu, bmv < thr);
    const __half* drow = g_d2h + (size_t)t * NTOK;

    int total = 0, first_k = -1;
    for (unsigned qm = qmask; qm; qm &= qm - 1) {
        int b = __ffs(qm) - 1;
        float2 vv = *reinterpret_cast<const float2*>(&drow[b * 128 + lane * 4]);
        __half2 h0 = reinterpret_cast<__half2&>(vv.x);
        __half2 h1 = reinterpret_cast<__half2&>(vv.y);
        float v[4] = { __low2float(h0), __high2float(h0), __low2float(h1), __high2float(h1) };
        #pragma unroll
        for (int s = 0; s < 4; s++) {
            unsigned m = __ballot_sync(0xFFFFFFFFu, v[s] < thr);
            if (!m) continue;
            int ldr = __ffs(m) - 1;
            if (total == 0) first_k = b * 128 + ldr * 4 + s;
            unsigned base = 0;
            if (lane == ldr) base = (unsigned)atomicAdd(&s_nwork, __popc(m));
            base = __shfl_sync(0xFFFFFFFFu, base, ldr);
            if (m & (1u << lane)) {
                unsigned pos = base + (unsigned)__popc(m & ((1u << lane) - 1));
                if (pos < WCAP)
                    s_work[pos] = ((unsigned)w << 12) | (unsigned)(b * 128 + lane * 4 + s);
            }
            total += __popc(m);
        }
    }
    if (lane == 0) { s_cnt[w] = total; s_first[w] = first_k; }
    __syncthreads();

    // Phase B: block-wide rescore of all worklist entries (skip unique tokens)
    int nwork = s_nwork; if (nwork > WCAP) nwork = WCAP;
    for (int e = w; e < nwork; e += 8) {
        unsigned ent = s_work[e];
        int tslot = ent >> 12, k = ent & 4095;
        if (s_cnt[tslot] <= 1) continue;
        const float4* za = (const float4*)(g_Zt + (size_t)(t0 + tslot) * DDIM);
        const float4* cb = (const float4*)(g_CBt + (size_t)k * DDIM);
        float sdot = 0.f;
        #pragma unroll
        for (int j = 0; j < 8; j++) {
            float4 a = za[j * 32 + lane], bb = cb[j * 32 + lane];
            sdot = fmaf(a.x, bb.x, sdot); sdot = fmaf(a.y, bb.y, sdot);
            sdot = fmaf(a.z, bb.z, sdot); sdot = fmaf(a.w, bb.w, sdot);
        }
        #pragma unroll
        for (int o = 16; o; o >>= 1) sdot += __shfl_xor_sync(0xFFFFFFFFu, sdot, o);
        if (lane == 0) {
            float d2 = fmaf(-2.f, sdot, g_cbnorm[k]);
            unsigned long long pk = ((unsigned long long)order_f32(d2) << 32) | (unsigned)k;
            atomicMin(&s_min[tslot], pk);
        }
    }
    __syncthreads();
    if (threadIdx.x < 8) {
        int ts = threadIdx.x;
        unsigned kk = (s_cnt[ts] <= 1) ? (unsigned)s_first[ts]
                                       : (unsigned)(s_min[ts] & 0xFFFFFFFFull);
        g_final[t0 + ts] = (unsigned long long)kk;
    }
}

// ---------------------------------------------------------------------------
// gather: contiguous reads of token-major g_CBt + smem transpose.
// grid (32 nb, 16 dc), 256 threads; block = 128 tokens x 64 dims.
// ---------------------------------------------------------------------------
__global__ void vq_gather(const float* __restrict__ Z, float* __restrict__ out, int writeQ) {
    __shared__ float qs[128][65];
    __shared__ int ks[128];
    const int nb = blockIdx.x, dc = blockIdx.y, tid = threadIdx.x;
    if (tid < 128) ks[tid] = (int)(g_final[nb * 128 + tid] & 0xFFFFFFFFu);
    __syncthreads();
    for (int idx = tid; idx < 128 * 64; idx += 256) {
        int n = idx >> 6, d = idx & 63;
        qs[n][d] = g_CBt[(size_t)ks[n] * DDIM + dc * 64 + d];
    }
    __syncthreads();
    float* out_q = out + (size_t)DDIM * NTOK;
    for (int idx = tid; idx < 64 * 128; idx += 256) {
        int d = idx >> 7, n = idx & 127;
        int gd = dc * 64 + d, gn = nb * 128 + n;
        float q = qs[n][d];
        float z = Z[(size_t)gd * NTOK + gn];
        out[(size_t)gd * NTOK + gn] = q + (z - q);
        if (writeQ) out_q[(size_t)gd * NTOK + gn] = q;
    }
}

// ---------------------------------------------------------------------------
extern "C" void kernel_launch(void* const* d_in, const int* in_sizes, int n_in,
                              void* d_out, int out_size) {
    const float* Z  = (const float*)d_in[0];
    const float* CB = (const float*)d_in[1];
    float* out = (float*)d_out;
    const int writeQ = (out_size >= 2 * DDIM * NTOK) ? 1 : 0;

    vq_prep<<<dim3(32, 16, 2), 256>>>(Z, CB);
    vq_norm_combine<<<16, 256>>>();
    vq_gemm<<<dim3(32, 32), 128>>>();
    vq_refine<<<512, 256>>>();
    vq_gather<<<dim3(32, 16), 256>>>(Z, out, writeQ);
}

// round 13
// speedup vs baseline: 1.6934x; 1.3391x over previous
#include <cuda_runtime.h>
#include <cuda_bf16.h>
#include <cuda_fp16.h>
#include <cstdint>

// VQ-VAE nearest-codebook quantization.
//   idx[n] = argmin_k (||cb_k||^2 - 2 z_n . cb_k);  zq = cb[idx];  z_st = zq + (z - zq)
// Coarse: int8 mma.sync (m16n8k32.s8, exact s32 dot of quantized values)
//         -> fp16 d2 + per-128-code block minima.
// Refine: block-balanced; candidates with coarse d2 < min + MARGIN; if >1 for a
// token, exact fp32 rescore picks the argmin (tie -> lowest k, = jnp.argmin).
// MARGIN 4.5 covers int8-quantization d2 error (pair-diff std ~0.7 -> 6σ).

#define NTOK 4096
#define DDIM 1024
#define MARGIN 4.5f
#define KBLK 32           // 4096 / 128 code-blocks
#define WCAP 2048         // worklist capacity per refine block (8 tokens)
#define Z_CLAMP 5.5f
#define NCHUNK 16         // K = 1024 int8 bytes, 64 per chunk

__device__ unsigned long long g_best[NTOK];     // coarse packed (ord(d2)<<32)|k
__device__ unsigned long long g_final[NTOK];    // chosen k (low 32 bits)
__device__ float g_cbnorm[NTOK];
__device__ float g_nrm_part[16][NTOK];
__device__ float g_blockmin[NTOK * KBLK];       // coarse min per (token, 128-code block)
__device__ float g_Zt[(size_t)NTOK * DDIM];     // fp32 token-major (rescore)
__device__ float g_CBt[(size_t)NTOK * DDIM];
__device__ __align__(16) int8_t g_Zq[(size_t)NTOK * DDIM];   // int8 row-major images
__device__ __align__(16) int8_t g_CBq[(size_t)NTOK * DDIM];
__device__ __half g_d2h[(size_t)NTOK * NTOK];   // coarse d2 [token][code], fp16

// ---- helpers ----
__device__ __forceinline__ uint32_t smem_u32(const void* p) {
    uint32_t a;
    asm("{ .reg .u64 t; cvta.to.shared.u64 t, %1; cvt.u32.u64 %0, t; }" : "=r"(a) : "l"(p));
    return a;
}
__device__ __forceinline__ unsigned order_f32(float f) {
    unsigned u = __float_as_uint(f);
    return (u & 0x80000000u) ? ~u : (u | 0x80000000u);
}
__device__ __forceinline__ float unorder_f32(unsigned u) {
    return (u & 0x80000000u) ? __uint_as_float(u ^ 0x80000000u) : __uint_as_float(~u);
}
__device__ __forceinline__ void cp_async16(uint32_t dst, const void* src) {
    asm volatile("cp.async.cg.shared.global [%0], [%1], 16;" :: "r"(dst), "l"(src));
}
__device__ __forceinline__ void cp_commit() { asm volatile("cp.async.commit_group;"); }
__device__ __forceinline__ void cp_wait1()  { asm volatile("cp.async.wait_group 1;"); }
__device__ __forceinline__ void ldsm4(uint32_t (&r)[4], uint32_t addr) {
    asm volatile("ldmatrix.sync.aligned.m8n8.x4.shared.b16 {%0,%1,%2,%3}, [%4];"
                 : "=r"(r[0]), "=r"(r[1]), "=r"(r[2]), "=r"(r[3]) : "r"(addr));
}
// int8 MMA: byte-level fragments identical to m16n8k16.bf16 (32B of K per step),
// so the same ldmatrix addressing feeds it correctly.
__device__ __forceinline__ void mma16832s8(int (&c)[4], const uint32_t (&a)[4],
                                           uint32_t b0, uint32_t b1) {
    asm volatile(
        "mma.sync.aligned.m16n8k32.row.col.s32.s8.s8.s32 "
        "{%0,%1,%2,%3}, {%4,%5,%6,%7}, {%8,%9}, {%0,%1,%2,%3};"
        : "+r"(c[0]), "+r"(c[1]), "+r"(c[2]), "+r"(c[3])
        : "r"(a[0]), "r"(a[1]), "r"(a[2]), "r"(a[3]), "r"(b0), "r"(b1));
}
// Swizzled smem tile: rows x 4 k-granules of 16B; 2 rows per 128B line,
// xor over ((row>>1)&7) -> conflict-free for cp.async stores and ldmatrix.
__device__ __forceinline__ uint32_t sw_addr(uint32_t base, int row, int kg) {
    return base + ((row >> 1) << 7) + ((((kg + ((row & 1) << 2)) ^ ((row >> 1) & 7))) << 4);
}

// ---------------------------------------------------------------------------
// prep: token-major fp32 + int8 row-major images + partial cb norms
// grid (32 nb, 16 dc, 2 which), 256 threads. Block = 128 cols x 64 dims.
// ---------------------------------------------------------------------------
__global__ void vq_prep(const float* __restrict__ Z, const float* __restrict__ CB) {
    __shared__ float tile[64 * 129];
    const int nb = blockIdx.x, dc = blockIdx.y, which = blockIdx.z;
    const float* src = which ? CB : Z;
    float* dstT = which ? g_CBt : g_Zt;
    int8_t* dstQ = which ? g_CBq : g_Zq;
    const int tid = threadIdx.x;

    for (int idx = tid; idx < 64 * 128; idx += 256) {
        int d = idx >> 7, n = idx & 127;
        tile[d * 129 + n] = src[(size_t)(dc * 64 + d) * NTOK + nb * 128 + n];
    }
    __syncthreads();
    for (int idx = tid; idx < 64 * 128; idx += 256) {
        int n = idx >> 6, d = idx & 63;
        dstT[(size_t)(nb * 128 + n) * DDIM + dc * 64 + d] = tile[d * 129 + n];
    }
    // int8 image: z scaled by 127/Z_CLAMP (clamped), cb by 127 (cb in [0,1))
    const float zs = 127.0f / Z_CLAMP;
    for (int idx = tid; idx < 128 * 16; idx += 256) {
        int n = idx >> 4, g = (idx & 15) << 2;       // dims g..g+3
        char4 c4;
        if (which) {
            c4.x = (char)__float2int_rn(tile[(g + 0) * 129 + n] * 127.0f);
            c4.y = (char)__float2int_rn(tile[(g + 1) * 129 + n] * 127.0f);
            c4.z = (char)__float2int_rn(tile[(g + 2) * 129 + n] * 127.0f);
            c4.w = (char)__float2int_rn(tile[(g + 3) * 129 + n] * 127.0f);
        } else {
            c4.x = (char)__float2int_rn(fminf(fmaxf(tile[(g + 0) * 129 + n], -Z_CLAMP), Z_CLAMP) * zs);
            c4.y = (char)__float2int_rn(fminf(fmaxf(tile[(g + 1) * 129 + n], -Z_CLAMP), Z_CLAMP) * zs);
            c4.z = (char)__float2int_rn(fminf(fmaxf(tile[(g + 2) * 129 + n], -Z_CLAMP), Z_CLAMP) * zs);
            c4.w = (char)__float2int_rn(fminf(fmaxf(tile[(g + 3) * 129 + n], -Z_CLAMP), Z_CLAMP) * zs);
        }
        *reinterpret_cast<char4*>(&dstQ[(size_t)(nb * 128 + n) * DDIM + dc * 64 + g]) = c4;
    }
    if (which && tid < 128) {
        float s = 0.f;
        #pragma unroll 8
        for (int d = 0; d < 64; d++) { float v = tile[d * 129 + tid]; s += v * v; }
        g_nrm_part[dc][nb * 128 + tid] = s;
    }
}

// combine norms + init coarse bests (after prep, before gemm)
__global__ void vq_norm_combine() {
    int k = blockIdx.x * 256 + threadIdx.x;
    float s = 0.f;
    #pragma unroll
    for (int i = 0; i < 16; i++) s += g_nrm_part[i][k];
    g_cbnorm[k] = s;
    g_best[k] = ~0ull;
}

// ---------------------------------------------------------------------------
// coarse GEMM: int8, 128 tokens x 128 codes x K=1024 bytes (64B chunks),
// 3-stage cp.async (48KB static smem). 128 threads = 4 warps (2M x 2N),
// warp tile 64x64, 2 CTAs/SM. Exact s32 dot; d2 = cbnorm - S2*dot.
// Epilogue: fp16 d2 + per-token block min.
// ---------------------------------------------------------------------------
#define STG_B 16384     // A 8KB + B 8KB per stage (128 rows x 64B each)

__global__ __launch_bounds__(128, 2) void vq_gemm() {
    __shared__ __align__(1024) char sm[3 * STG_B];
    const uint32_t smb = smem_u32(sm);
    const int tid = threadIdx.x, wid = tid >> 5, lane = tid & 31;
    const int warp_m = wid & 1, warp_n = wid >> 1;       // 2 x 2
    const int t0 = blockIdx.x * 128, k0 = blockIdx.y * 128;
    const char* zp = (const char*)g_Zq + (size_t)t0 * DDIM;
    const char* cp = (const char*)g_CBq + (size_t)k0 * DDIM;

    int acc[4][8][4];
    #pragma unroll
    for (int i = 0; i < 4; i++)
        #pragma unroll
        for (int j = 0; j < 8; j++)
            #pragma unroll
            for (int q = 0; q < 4; q++) acc[i][j][q] = 0;

    // stage loader: 1024 granules of 16B, 8 per thread (row stride 1024B)
    auto load_stage = [&](int stg, int kc) {
        const uint32_t sbase = smb + stg * STG_B;
        #pragma unroll
        for (int u = 0; u < 8; u++) {
            int i = tid + u * 128;
            int r = (i >> 2) & 127;
            int c = i & 3;
            bool isB = i >= 512;
            uint32_t dst = sw_addr(sbase + (isB ? 8192 : 0), r, c);
            const char* src = (isB ? cp : zp) + (size_t)r * DDIM + kc * 64 + c * 16;
            cp_async16(dst, src);
        }
        cp_commit();
    };

    load_stage(0, 0);
    load_stage(1, 1);

    for (int kc = 0; kc < NCHUNK; kc++) {
        cp_wait1();              // stage kc resident (own thread's ops)
        __syncthreads();         // all threads' stores visible; ring slot free
        if (kc + 2 < NCHUNK) load_stage((kc + 2) % 3, kc + 2);
        else cp_commit();        // empty group keeps wait_group 1 aligned

        const uint32_t sA = smb + (kc % 3) * STG_B;
        const uint32_t sB = sA + 8192;
        #pragma unroll
        for (int s = 0; s < 2; s++) {       // two k32 steps (32B each)
            uint32_t a[4][4], b[4][4];
            #pragma unroll
            for (int mt = 0; mt < 4; mt++) {
                int row = warp_m * 64 + mt * 16 + ((lane >> 3) & 1) * 8 + (lane & 7);
                int kg = s * 2 + (lane >> 4);
                ldsm4(a[mt], sw_addr(sA, row, kg));
            }
            #pragma unroll
            for (int np = 0; np < 4; np++) {
                int row = warp_n * 64 + np * 16 + ((lane >> 4) << 3) + (lane & 7);
                int kg = s * 2 + ((lane >> 3) & 1);
                ldsm4(b[np], sw_addr(sB, row, kg));
            }
            #pragma unroll
            for (int mt = 0; mt < 4; mt++) {
                #pragma unroll
                for (int np = 0; np < 4; np++) {
                    mma16832s8(acc[mt][np * 2 + 0], a[mt], b[np][0], b[np][1]);
                    mma16832s8(acc[mt][np * 2 + 1], a[mt], b[np][2], b[np][3]);
                }
            }
        }
    }

    // ---- epilogue: d2 = cbnorm[k] - S2*dot_int -> fp16 store + block minima ----
    const float S2 = 2.0f * (Z_CLAMP / 127.0f) * (1.0f / 127.0f);
    const int kbase = k0 + warp_n * 64 + (lane & 3) * 2;
    float2 cbn[8];
    #pragma unroll
    for (int nt = 0; nt < 8; nt++)
        cbn[nt] = *reinterpret_cast<const float2*>(&g_cbnorm[kbase + nt * 8]);

    unsigned long long* smin = reinterpret_cast<unsigned long long*>(sm);  // 128*2 u64

    #pragma unroll
    for (int mt = 0; mt < 4; mt++) {
        #pragma unroll
        for (int half = 0; half < 2; half++) {
            const int tl = warp_m * 64 + mt * 16 + half * 8 + (lane >> 2);
            __half* drow = g_d2h + (size_t)(t0 + tl) * NTOK;
            unsigned long long best = ~0ull;
            #pragma unroll
            for (int nt = 0; nt < 8; nt++) {
                float dx = fmaf(-S2, (float)acc[mt][nt][half * 2 + 0], cbn[nt].x);
                float dy = fmaf(-S2, (float)acc[mt][nt][half * 2 + 1], cbn[nt].y);
                *reinterpret_cast<__half2*>(&drow[kbase + nt * 8]) = __floats2half2_rn(dx, dy);
                unsigned long long p0 =
                    ((unsigned long long)order_f32(dx) << 32) | (unsigned)(kbase + nt * 8);
                unsigned long long p1 =
                    ((unsigned long long)order_f32(dy) << 32) | (unsigned)(kbase + nt * 8 + 1);
                if (p0 < best) best = p0;
                if (p1 < best) best = p1;
            }
            {
                unsigned long long v = __shfl_xor_sync(0xFFFFFFFFu, best, 1);
                if (v < best) best = v;
                v = __shfl_xor_sync(0xFFFFFFFFu, best, 2);
                if (v < best) best = v;
            }
            if ((lane & 3) == 0) smin[tl * 2 + warp_n] = best;
        }
    }
    __syncthreads();
    if (tid < 128) {
        unsigned long long b = smin[tid * 2];
        if (smin[tid * 2 + 1] < b) b = smin[tid * 2 + 1];
        atomicMin(&g_best[t0 + tid], b);
        g_blockmin[(t0 + tid) * KBLK + blockIdx.y] = unorder_f32((unsigned)(b >> 32));
    }
}

// ---------------------------------------------------------------------------
// refine: block = 8 tokens, 8 warps. Phase A: each warp classifies its token,
// pushing all candidates (coarse d2 < min + MARGIN) into a shared worklist.
// Phase B: all warps drain the worklist (exact fp32 dot, smem atomicMin).
// Tokens with a single candidate skip rescore (margin proof: it IS the argmin).
// ---------------------------------------------------------------------------
__global__ __launch_bounds__(256) void vq_refine() {
    __shared__ unsigned s_work[WCAP];            // (tslot<<12) | k
    __shared__ int s_nwork;
    __shared__ int s_cnt[8];
    __shared__ int s_first[8];
    __shared__ unsigned long long s_min[8];
    const int w = threadIdx.x >> 5, lane = threadIdx.x & 31;
    const int t0 = blockIdx.x * 8;
    const int t = t0 + w;

    if (threadIdx.x == 0) s_nwork = 0;
    if (threadIdx.x < 8) s_min[threadIdx.x] = ~0ull;
    __syncthreads();

    const float thr = unorder_f32((unsigned)(g_best[t] >> 32)) + MARGIN;
    const float bmv = g_blockmin[t * KBLK + lane];
    unsigned qmask = __ballot_sync(0xFFFFFFFFu, bmv < thr);
    const __half* drow = g_d2h + (size_t)t * NTOK;

    int total = 0, first_k = -1;
    for (unsigned qm = qmask; qm; qm &= qm - 1) {
        int b = __ffs(qm) - 1;
        float2 vv = *reinterpret_cast<const float2*>(&drow[b * 128 + lane * 4]);
        __half2 h0 = reinterpret_cast<__half2&>(vv.x);
        __half2 h1 = reinterpret_cast<__half2&>(vv.y);
        float v[4] = { __low2float(h0), __high2float(h0), __low2float(h1), __high2float(h1) };
        #pragma unroll
        for (int s = 0; s < 4; s++) {
            unsigned m = __ballot_sync(0xFFFFFFFFu, v[s] < thr);
            if (!m) continue;
            int ldr = __ffs(m) - 1;
            if (total == 0) first_k = b * 128 + ldr * 4 + s;
            unsigned base = 0;
            if (lane == ldr) base = (unsigned)atomicAdd(&s_nwork, __popc(m));
            base = __shfl_sync(0xFFFFFFFFu, base, ldr);
            if (m & (1u << lane)) {
                unsigned pos = base + (unsigned)__popc(m & ((1u << lane) - 1));
                if (pos < WCAP)
                    s_work[pos] = ((unsigned)w << 12) | (unsigned)(b * 128 + lane * 4 + s);
            }
            total += __popc(m);
        }
    }
    if (lane == 0) { s_cnt[w] = total; s_first[w] = first_k; }
    __syncthreads();

    // Phase B: block-wide rescore of all worklist entries (skip unique tokens)
    int nwork = s_nwork; if (nwork > WCAP) nwork = WCAP;
    for (int e = w; e < nwork; e += 8) {
        unsigned ent = s_work[e];
        int tslot = ent >> 12, k = ent & 4095;
        if (s_cnt[tslot] <= 1) continue;
        const float4* za = (const float4*)(g_Zt + (size_t)(t0 + tslot) * DDIM);
        const float4* cb = (const float4*)(g_CBt + (size_t)k * DDIM);
        float sdot = 0.f;
        #pragma unroll
        for (int j = 0; j < 8; j++) {
            float4 a = za[j * 32 + lane], bb = cb[j * 32 + lane];
            sdot = fmaf(a.x, bb.x, sdot); sdot = fmaf(a.y, bb.y, sdot);
            sdot = fmaf(a.z, bb.z, sdot); sdot = fmaf(a.w, bb.w, sdot);
        }
        #pragma unroll
        for (int o = 16; o; o >>= 1) sdot += __shfl_xor_sync(0xFFFFFFFFu, sdot, o);
        if (lane == 0) {
            float d2 = fmaf(-2.f, sdot, g_cbnorm[k]);
            unsigned long long pk = ((unsigned long long)order_f32(d2) << 32) | (unsigned)k;
            atomicMin(&s_min[tslot], pk);
        }
    }
    __syncthreads();
    if (threadIdx.x < 8) {
        int ts = threadIdx.x;
        unsigned kk = (s_cnt[ts] <= 1) ? (unsigned)s_first[ts]
                                       : (unsigned)(s_min[ts] & 0xFFFFFFFFull);
        g_final[t0 + ts] = (unsigned long long)kk;
    }
}

// ---------------------------------------------------------------------------
// gather: contiguous reads of token-major g_CBt + smem transpose.
// grid (32 nb, 16 dc), 256 threads; block = 128 tokens x 64 dims.
// ---------------------------------------------------------------------------
__global__ void vq_gather(const float* __restrict__ Z, float* __restrict__ out, int writeQ) {
    __shared__ float qs[128][65];
    __shared__ int ks[128];
    const int nb = blockIdx.x, dc = blockIdx.y, tid = threadIdx.x;
    if (tid < 128) ks[tid] = (int)(g_final[nb * 128 + tid] & 0xFFFFFFFFu);
    __syncthreads();
    for (int idx = tid; idx < 128 * 64; idx += 256) {
        int n = idx >> 6, d = idx & 63;
        qs[n][d] = g_CBt[(size_t)ks[n] * DDIM + dc * 64 + d];
    }
    __syncthreads();
    float* out_q = out + (size_t)DDIM * NTOK;
    for (int idx = tid; idx < 64 * 128; idx += 256) {
        int d = idx >> 7, n = idx & 127;
        int gd = dc * 64 + d, gn = nb * 128 + n;
        float q = qs[n][d];
        float z = Z[(size_t)gd * NTOK + gn];
        out[(size_t)gd * NTOK + gn] = q + (z - q);
        if (writeQ) out_q[(size_t)gd * NTOK + gn] = q;
    }
}

// ---------------------------------------------------------------------------
extern "C" void kernel_launch(void* const* d_in, const int* in_sizes, int n_in,
                              void* d_out, int out_size) {
    const float* Z  = (const float*)d_in[0];
    const float* CB = (const float*)d_in[1];
    float* out = (float*)d_out;
    const int writeQ = (out_size >= 2 * DDIM * NTOK) ? 1 : 0;

    vq_prep<<<dim3(32, 16, 2), 256>>>(Z, CB);
    vq_norm_combine<<<16, 256>>>();
    vq_gemm<<<dim3(32, 32), 128>>>();
    vq_refine<<<512, 256>>>();
    vq_gather<<<dim3(32, 16), 256>>>(Z, out, writeQ);
}

// round 14
// speedup vs baseline: 1.7233x; 1.0177x over previous
#include <cuda_runtime.h>
#include <cuda_bf16.h>
#include <cuda_fp16.h>
#include <cstdint>

// VQ-VAE nearest-codebook quantization.
//   idx[n] = argmin_k (||cb_k||^2 - 2 z_n . cb_k);  zq = cb[idx];  z_st = zq + (z - zq)
// Coarse: int8 mma.sync (m16n8k32.s8, exact s32 dot of quantized values)
//         -> fp16 d2 + per-128-code block minima.
// Refine: block-balanced; candidates with coarse d2 < min + MARGIN; if >1 for a
// token, exact fp32 rescore picks the argmin (tie -> lowest k, = jnp.argmin).
// MARGIN 3.5: pair-diff coarse-error std ~0.36 -> 6σ=2.2, +fp16 slack 0.5.

#define NTOK 4096
#define DDIM 1024
#define MARGIN 3.5f
#define KBLK 32           // 4096 / 128 code-blocks
#define WCAP 2048         // worklist capacity per refine block (8 tokens)
#define Z_CLAMP 5.5f
#define NCHUNK 16         // K = 1024 int8 bytes, 64 per chunk

__device__ unsigned long long g_best[NTOK];     // coarse packed (ord(d2)<<32)|k
__device__ unsigned long long g_final[NTOK];    // chosen k (low 32 bits)
__device__ float g_cbnorm[NTOK];
__device__ float g_nrm_part[16][NTOK];
__device__ float g_blockmin[NTOK * KBLK];       // coarse min per (token, 128-code block)
__device__ float g_Zt[(size_t)NTOK * DDIM];     // fp32 token-major (rescore)
__device__ float g_CBt[(size_t)NTOK * DDIM];
__device__ __align__(16) int8_t g_Zq[(size_t)NTOK * DDIM];   // int8 row-major images
__device__ __align__(16) int8_t g_CBq[(size_t)NTOK * DDIM];
__device__ __half g_d2h[(size_t)NTOK * NTOK];   // coarse d2 [token][code], fp16

// ---- helpers ----
__device__ __forceinline__ uint32_t smem_u32(const void* p) {
    uint32_t a;
    asm("{ .reg .u64 t; cvta.to.shared.u64 t, %1; cvt.u32.u64 %0, t; }" : "=r"(a) : "l"(p));
    return a;
}
__device__ __forceinline__ unsigned order_f32(float f) {
    unsigned u = __float_as_uint(f);
    return (u & 0x80000000u) ? ~u : (u | 0x80000000u);
}
__device__ __forceinline__ float unorder_f32(unsigned u) {
    return (u & 0x80000000u) ? __uint_as_float(u ^ 0x80000000u) : __uint_as_float(~u);
}
__device__ __forceinline__ void cp_async16(uint32_t dst, const void* src) {
    asm volatile("cp.async.cg.shared.global [%0], [%1], 16;" :: "r"(dst), "l"(src));
}
__device__ __forceinline__ void cp_commit() { asm volatile("cp.async.commit_group;"); }
__device__ __forceinline__ void cp_wait1()  { asm volatile("cp.async.wait_group 1;"); }
__device__ __forceinline__ void ldsm4(uint32_t (&r)[4], uint32_t addr) {
    asm volatile("ldmatrix.sync.aligned.m8n8.x4.shared.b16 {%0,%1,%2,%3}, [%4];"
                 : "=r"(r[0]), "=r"(r[1]), "=r"(r[2]), "=r"(r[3]) : "r"(addr));
}
// int8 MMA: byte-level fragments identical to m16n8k16.bf16 (32B of K per step),
// so the same ldmatrix addressing feeds it correctly.
__device__ __forceinline__ void mma16832s8(int (&c)[4], const uint32_t (&a)[4],
                                           uint32_t b0, uint32_t b1) {
    asm volatile(
        "mma.sync.aligned.m16n8k32.row.col.s32.s8.s8.s32 "
        "{%0,%1,%2,%3}, {%4,%5,%6,%7}, {%8,%9}, {%0,%1,%2,%3};"
        : "+r"(c[0]), "+r"(c[1]), "+r"(c[2]), "+r"(c[3])
        : "r"(a[0]), "r"(a[1]), "r"(a[2]), "r"(a[3]), "r"(b0), "r"(b1));
}
// Swizzled smem tile: rows x 4 k-granules of 16B; 2 rows per 128B line,
// xor over ((row>>1)&7) -> conflict-free for cp.async stores and ldmatrix.
__device__ __forceinline__ uint32_t sw_addr(uint32_t base, int row, int kg) {
    return base + ((row >> 1) << 7) + ((((kg + ((row & 1) << 2)) ^ ((row >> 1) & 7))) << 4);
}

// ---------------------------------------------------------------------------
// prep: token-major fp32 + int8 row-major images + partial cb norms
// grid (32 nb, 16 dc, 2 which), 256 threads. Block = 128 cols x 64 dims.
// ---------------------------------------------------------------------------
__global__ void vq_prep(const float* __restrict__ Z, const float* __restrict__ CB) {
    __shared__ float tile[64 * 129];
    const int nb = blockIdx.x, dc = blockIdx.y, which = blockIdx.z;
    const float* src = which ? CB : Z;
    float* dstT = which ? g_CBt : g_Zt;
    int8_t* dstQ = which ? g_CBq : g_Zq;
    const int tid = threadIdx.x;

    for (int idx = tid; idx < 64 * 128; idx += 256) {
        int d = idx >> 7, n = idx & 127;
        tile[d * 129 + n] = src[(size_t)(dc * 64 + d) * NTOK + nb * 128 + n];
    }
    __syncthreads();
    for (int idx = tid; idx < 64 * 128; idx += 256) {
        int n = idx >> 6, d = idx & 63;
        dstT[(size_t)(nb * 128 + n) * DDIM + dc * 64 + d] = tile[d * 129 + n];
    }
    // int8 image: z scaled by 127/Z_CLAMP (clamped), cb by 127 (cb in [0,1))
    const float zs = 127.0f / Z_CLAMP;
    for (int idx = tid; idx < 128 * 16; idx += 256) {
        int n = idx >> 4, g = (idx & 15) << 2;       // dims g..g+3
        char4 c4;
        if (which) {
            c4.x = (char)__float2int_rn(tile[(g + 0) * 129 + n] * 127.0f);
            c4.y = (char)__float2int_rn(tile[(g + 1) * 129 + n] * 127.0f);
            c4.z = (char)__float2int_rn(tile[(g + 2) * 129 + n] * 127.0f);
            c4.w = (char)__float2int_rn(tile[(g + 3) * 129 + n] * 127.0f);
        } else {
            c4.x = (char)__float2int_rn(fminf(fmaxf(tile[(g + 0) * 129 + n], -Z_CLAMP), Z_CLAMP) * zs);
            c4.y = (char)__float2int_rn(fminf(fmaxf(tile[(g + 1) * 129 + n], -Z_CLAMP), Z_CLAMP) * zs);
            c4.z = (char)__float2int_rn(fminf(fmaxf(tile[(g + 2) * 129 + n], -Z_CLAMP), Z_CLAMP) * zs);
            c4.w = (char)__float2int_rn(fminf(fmaxf(tile[(g + 3) * 129 + n], -Z_CLAMP), Z_CLAMP) * zs);
        }
        *reinterpret_cast<char4*>(&dstQ[(size_t)(nb * 128 + n) * DDIM + dc * 64 + g]) = c4;
    }
    if (which && tid < 128) {
        float s = 0.f;
        #pragma unroll 8
        for (int d = 0; d < 64; d++) { float v = tile[d * 129 + tid]; s += v * v; }
        g_nrm_part[dc][nb * 128 + tid] = s;
    }
}

// combine norms + init coarse bests (after prep, before gemm)
__global__ void vq_norm_combine() {
    int k = blockIdx.x * 256 + threadIdx.x;
    float s = 0.f;
    #pragma unroll
    for (int i = 0; i < 16; i++) s += g_nrm_part[i][k];
    g_cbnorm[k] = s;
    g_best[k] = ~0ull;
}

// ---------------------------------------------------------------------------
// coarse GEMM: int8, 128 tokens x 128 codes x K=1024 bytes (64B chunks),
// 3-stage cp.async (48KB static smem). 128 threads = 4 warps (2M x 2N),
// warp tile 64x64, 2 CTAs/SM. Exact s32 dot; d2 = cbnorm - S2*dot.
// Epilogue: fp16 d2 + per-token block min.
// ---------------------------------------------------------------------------
#define STG_B 16384     // A 8KB + B 8KB per stage (128 rows x 64B each)

__global__ __launch_bounds__(128, 2) void vq_gemm() {
    __shared__ __align__(1024) char sm[3 * STG_B];
    const uint32_t smb = smem_u32(sm);
    const int tid = threadIdx.x, wid = tid >> 5, lane = tid & 31;
    const int warp_m = wid & 1, warp_n = wid >> 1;       // 2 x 2
    const int t0 = blockIdx.x * 128, k0 = blockIdx.y * 128;
    const char* zp = (const char*)g_Zq + (size_t)t0 * DDIM;
    const char* cp = (const char*)g_CBq + (size_t)k0 * DDIM;

    int acc[4][8][4];
    #pragma unroll
    for (int i = 0; i < 4; i++)
        #pragma unroll
        for (int j = 0; j < 8; j++)
            #pragma unroll
            for (int q = 0; q < 4; q++) acc[i][j][q] = 0;

    // stage loader: 1024 granules of 16B, 8 per thread (row stride 1024B)
    auto load_stage = [&](int stg, int kc) {
        const uint32_t sbase = smb + stg * STG_B;
        #pragma unroll
        for (int u = 0; u < 8; u++) {
            int i = tid + u * 128;
            int r = (i >> 2) & 127;
            int c = i & 3;
            bool isB = i >= 512;
            uint32_t dst = sw_addr(sbase + (isB ? 8192 : 0), r, c);
            const char* src = (isB ? cp : zp) + (size_t)r * DDIM + kc * 64 + c * 16;
            cp_async16(dst, src);
        }
        cp_commit();
    };

    load_stage(0, 0);
    load_stage(1, 1);

    for (int kc = 0; kc < NCHUNK; kc++) {
        cp_wait1();              // stage kc resident (own thread's ops)
        __syncthreads();         // all threads' stores visible; ring slot free
        if (kc + 2 < NCHUNK) load_stage((kc + 2) % 3, kc + 2);
        else cp_commit();        // empty group keeps wait_group 1 aligned

        const uint32_t sA = smb + (kc % 3) * STG_B;
        const uint32_t sB = sA + 8192;
        #pragma unroll
        for (int s = 0; s < 2; s++) {       // two k32 steps (32B each)
            uint32_t a[4][4], b[4][4];
            #pragma unroll
            for (int mt = 0; mt < 4; mt++) {
                int row = warp_m * 64 + mt * 16 + ((lane >> 3) & 1) * 8 + (lane & 7);
                int kg = s * 2 + (lane >> 4);
                ldsm4(a[mt], sw_addr(sA, row, kg));
            }
            #pragma unroll
            for (int np = 0; np < 4; np++) {
                int row = warp_n * 64 + np * 16 + ((lane >> 4) << 3) + (lane & 7);
                int kg = s * 2 + ((lane >> 3) & 1);
                ldsm4(b[np], sw_addr(sB, row, kg));
            }
            #pragma unroll
            for (int mt = 0; mt < 4; mt++) {
                #pragma unroll
                for (int np = 0; np < 4; np++) {
                    mma16832s8(acc[mt][np * 2 + 0], a[mt], b[np][0], b[np][1]);
                    mma16832s8(acc[mt][np * 2 + 1], a[mt], b[np][2], b[np][3]);
                }
            }
        }
    }

    // ---- epilogue: d2 = cbnorm[k] - S2*dot_int -> fp16 store + block minima ----
    const float S2 = 2.0f * (Z_CLAMP / 127.0f) * (1.0f / 127.0f);
    const int kbase = k0 + warp_n * 64 + (lane & 3) * 2;
    float2 cbn[8];
    #pragma unroll
    for (int nt = 0; nt < 8; nt++)
        cbn[nt] = *reinterpret_cast<const float2*>(&g_cbnorm[kbase + nt * 8]);

    unsigned long long* smin = reinterpret_cast<unsigned long long*>(sm);  // 128*2 u64

    #pragma unroll
    for (int mt = 0; mt < 4; mt++) {
        #pragma unroll
        for (int half = 0; half < 2; half++) {
            const int tl = warp_m * 64 + mt * 16 + half * 8 + (lane >> 2);
            __half* drow = g_d2h + (size_t)(t0 + tl) * NTOK;
            unsigned long long best = ~0ull;
            #pragma unroll
            for (int nt = 0; nt < 8; nt++) {
                float dx = fmaf(-S2, (float)acc[mt][nt][half * 2 + 0], cbn[nt].x);
                float dy = fmaf(-S2, (float)acc[mt][nt][half * 2 + 1], cbn[nt].y);
                *reinterpret_cast<__half2*>(&drow[kbase + nt * 8]) = __floats2half2_rn(dx, dy);
                unsigned long long p0 =
                    ((unsigned long long)order_f32(dx) << 32) | (unsigned)(kbase + nt * 8);
                unsigned long long p1 =
                    ((unsigned long long)order_f32(dy) << 32) | (unsigned)(kbase + nt * 8 + 1);
                if (p0 < best) best = p0;
                if (p1 < best) best = p1;
            }
            {
                unsigned long long v = __shfl_xor_sync(0xFFFFFFFFu, best, 1);
                if (v < best) best = v;
                v = __shfl_xor_sync(0xFFFFFFFFu, best, 2);
                if (v < best) best = v;
            }
            if ((lane & 3) == 0) smin[tl * 2 + warp_n] = best;
        }
    }
    __syncthreads();
    if (tid < 128) {
        unsigned long long b = smin[tid * 2];
        if (smin[tid * 2 + 1] < b) b = smin[tid * 2 + 1];
        atomicMin(&g_best[t0 + tid], b);
        g_blockmin[(t0 + tid) * KBLK + blockIdx.y] = unorder_f32((unsigned)(b >> 32));
    }
}

// ---------------------------------------------------------------------------
// refine: block = 8 tokens, 8 warps. Phase A: each warp classifies its token,
// pushing all candidates (coarse d2 < min + MARGIN) into a shared worklist;
// multi-candidate tokens cache their fp32 z row in smem (one DRAM read).
// Phase B: all warps drain the worklist (exact fp32 dot: smem z + global cb).
// Tokens with a single candidate skip rescore (margin proof: it IS the argmin).
// ---------------------------------------------------------------------------
__global__ __launch_bounds__(256) void vq_refine() {
    __shared__ float s_z[8][DDIM];               // 32KB: cached z rows
    __shared__ unsigned s_work[WCAP];            // (tslot<<12) | k
    __shared__ int s_nwork;
    __shared__ int s_cnt[8];
    __shared__ int s_first[8];
    __shared__ unsigned long long s_min[8];
    const int w = threadIdx.x >> 5, lane = threadIdx.x & 31;
    const int t0 = blockIdx.x * 8;
    const int t = t0 + w;

    if (threadIdx.x == 0) s_nwork = 0;
    if (threadIdx.x < 8) s_min[threadIdx.x] = ~0ull;
    __syncthreads();

    const float thr = unorder_f32((unsigned)(g_best[t] >> 32)) + MARGIN;
    const float bmv = g_blockmin[t * KBLK + lane];
    unsigned qmask = __ballot_sync(0xFFFFFFFFu, bmv < thr);
    const __half* drow = g_d2h + (size_t)t * NTOK;

    int total = 0, first_k = -1;
    for (unsigned qm = qmask; qm; qm &= qm - 1) {
        int b = __ffs(qm) - 1;
        float2 vv = *reinterpret_cast<const float2*>(&drow[b * 128 + lane * 4]);
        __half2 h0 = reinterpret_cast<__half2&>(vv.x);
        __half2 h1 = reinterpret_cast<__half2&>(vv.y);
        float v[4] = { __low2float(h0), __high2float(h0), __low2float(h1), __high2float(h1) };
        #pragma unroll
        for (int s = 0; s < 4; s++) {
            unsigned m = __ballot_sync(0xFFFFFFFFu, v[s] < thr);
            if (!m) continue;
            int ldr = __ffs(m) - 1;
            if (total == 0) first_k = b * 128 + ldr * 4 + s;
            unsigned base = 0;
            if (lane == ldr) base = (unsigned)atomicAdd(&s_nwork, __popc(m));
            base = __shfl_sync(0xFFFFFFFFu, base, ldr);
            if (m & (1u << lane)) {
                unsigned pos = base + (unsigned)__popc(m & ((1u << lane) - 1));
                if (pos < WCAP)
                    s_work[pos] = ((unsigned)w << 12) | (unsigned)(b * 128 + lane * 4 + s);
            }
            total += __popc(m);
        }
    }
    if (lane == 0) { s_cnt[w] = total; s_first[w] = first_k; }
    // multi-candidate tokens: cache z row in smem (warp-uniform condition)
    if (total > 1) {
        const float4* zsrc = (const float4*)(g_Zt + (size_t)t * DDIM);
        float4* zdst = (float4*)s_z[w];
        #pragma unroll
        for (int j = 0; j < 8; j++) zdst[j * 32 + lane] = zsrc[j * 32 + lane];
    }
    __syncthreads();

    // Phase B: block-wide rescore of all worklist entries (skip unique tokens)
    int nwork = s_nwork; if (nwork > WCAP) nwork = WCAP;
    for (int e = w; e < nwork; e += 8) {
        unsigned ent = s_work[e];
        int tslot = ent >> 12, k = ent & 4095;
        if (s_cnt[tslot] <= 1) continue;
        const float4* za = (const float4*)s_z[tslot];
        const float4* cb = (const float4*)(g_CBt + (size_t)k * DDIM);
        float sdot = 0.f;
        #pragma unroll
        for (int j = 0; j < 8; j++) {
            float4 a = za[j * 32 + lane], bb = cb[j * 32 + lane];
            sdot = fmaf(a.x, bb.x, sdot); sdot = fmaf(a.y, bb.y, sdot);
            sdot = fmaf(a.z, bb.z, sdot); sdot = fmaf(a.w, bb.w, sdot);
        }
        #pragma unroll
        for (int o = 16; o; o >>= 1) sdot += __shfl_xor_sync(0xFFFFFFFFu, sdot, o);
        if (lane == 0) {
            float d2 = fmaf(-2.f, sdot, g_cbnorm[k]);
            unsigned long long pk = ((unsigned long long)order_f32(d2) << 32) | (unsigned)k;
            atomicMin(&s_min[tslot], pk);
        }
    }
    __syncthreads();
    if (threadIdx.x < 8) {
        int ts = threadIdx.x;
        unsigned kk = (s_cnt[ts] <= 1) ? (unsigned)s_first[ts]
                                       : (unsigned)(s_min[ts] & 0xFFFFFFFFull);
        g_final[t0 + ts] = (unsigned long long)kk;
    }
}

// ---------------------------------------------------------------------------
// gather: contiguous reads of token-major g_CBt + smem transpose.
// grid (32 nb, 16 dc), 256 threads; block = 128 tokens x 64 dims.
// ---------------------------------------------------------------------------
__global__ void vq_gather(const float* __restrict__ Z, float* __restrict__ out, int writeQ) {
    __shared__ float qs[128][65];
    __shared__ int ks[128];
    const int nb = blockIdx.x, dc = blockIdx.y, tid = threadIdx.x;
    if (tid < 128) ks[tid] = (int)(g_final[nb * 128 + tid] & 0xFFFFFFFFu);
    __syncthreads();
    for (int idx = tid; idx < 128 * 64; idx += 256) {
        int n = idx >> 6, d = idx & 63;
        qs[n][d] = g_CBt[(size_t)ks[n] * DDIM + dc * 64 + d];
    }
    __syncthreads();
    float* out_q = out + (size_t)DDIM * NTOK;
    for (int idx = tid; idx < 64 * 128; idx += 256) {
        int d = idx >> 7, n = idx & 127;
        int gd = dc * 64 + d, gn = nb * 128 + n;
        float q = qs[n][d];
        float z = Z[(size_t)gd * NTOK + gn];
        out[(size_t)gd * NTOK + gn] = q + (z - q);
        if (writeQ) out_q[(size_t)gd * NTOK + gn] = q;
    }
}

// ---------------------------------------------------------------------------
extern "C" void kernel_launch(void* const* d_in, const int* in_sizes, int n_in,
                              void* d_out, int out_size) {
    const float* Z  = (const float*)d_in[0];
    const float* CB = (const float*)d_in[1];
    float* out = (float*)d_out;
    const int writeQ = (out_size >= 2 * DDIM * NTOK) ? 1 : 0;

    vq_prep<<<dim3(32, 16, 2), 256>>>(Z, CB);
    vq_norm_combine<<<16, 256>>>();
    vq_gemm<<<dim3(32, 32), 128>>>();
    vq_refine<<<512, 256>>>();
    vq_gather<<<dim3(32, 16), 256>>>(Z, out, writeQ);
}